// round 1
// baseline (speedup 1.0000x reference)
#include <cuda_runtime.h>
#include <math.h>

#define BDIM 2
#define TDIM 2048
#define CDIM 1024
#define NH 16
#define HD 64
#define MDIM (BDIM*TDIM)   // 4096
#define NQKV (3*CDIM)      // 3072

// Scratch (allocation-free rule: __device__ globals)
__device__ float g_q[BDIM*NH*TDIM*HD];
__device__ float g_k[BDIM*NH*TDIM*HD];
__device__ float g_v[BDIM*NH*TDIM*HD];
__device__ float g_y[MDIM*CDIM];

// ---------------- GEMM tile config ----------------
#define BM 128
#define BN 64
#define BK 16
#define TM 8
#define TN 4
// 256 threads = 16 thread-rows x 16 thread-cols

// ---------------- Kernel 1: QKV GEMM + RoPE epilogue ----------------
__global__ __launch_bounds__(256) void qkv_rope_kernel(
    const float* __restrict__ x,      // [4096,1024]
    const float* __restrict__ W,      // [1024,3072]
    const float* __restrict__ sinp,   // [2048,64]
    const float* __restrict__ cosp)   // [2048,64]
{
    __shared__ float As[BM][BK];
    __shared__ float Bs[BK][BN];
    const int tid = threadIdx.x;
    const int tr = tid >> 4;          // 0..15
    const int tc = tid & 15;          // 0..15
    const int m0 = blockIdx.y * BM;
    const int n0 = blockIdx.x * BN;

    float acc[TM][TN];
    #pragma unroll
    for (int i = 0; i < TM; i++)
        #pragma unroll
        for (int j = 0; j < TN; j++) acc[i][j] = 0.f;

    for (int k0 = 0; k0 < CDIM; k0 += BK) {
        #pragma unroll
        for (int i = 0; i < 8; i++) {               // 128*16 = 2048 elems
            int idx = tid + i * 256;
            int r = idx >> 4, c = idx & 15;
            As[r][c] = x[(m0 + r) * CDIM + k0 + c];
        }
        #pragma unroll
        for (int i = 0; i < 4; i++) {               // 16*64 = 1024 elems
            int idx = tid + i * 256;
            int r = idx >> 6, c = idx & 63;
            Bs[r][c] = W[(k0 + r) * NQKV + n0 + c];
        }
        __syncthreads();
        #pragma unroll
        for (int kk = 0; kk < BK; kk++) {
            float a[TM], b[TN];
            #pragma unroll
            for (int i = 0; i < TM; i++) a[i] = As[tr * TM + i][kk];
            #pragma unroll
            for (int j = 0; j < TN; j++) b[j] = Bs[kk][tc * TN + j];
            #pragma unroll
            for (int i = 0; i < TM; i++)
                #pragma unroll
                for (int j = 0; j < TN; j++)
                    acc[i][j] = fmaf(a[i], b[j], acc[i][j]);
        }
        __syncthreads();
    }

    // Epilogue: scatter into [B,NH,T,HD] with RoPE on q,k
    const int ncol0 = n0 + tc * TN;       // multiple of 4
    const int sec   = ncol0 >> 10;        // 0=q, 1=k, 2=v
    const int c0    = ncol0 & 1023;
    const int h     = c0 >> 6;
    const int d0    = c0 & 63;            // even, multiple of 4
    float* dst = (sec == 0) ? g_q : (sec == 1 ? g_k : g_v);

    #pragma unroll
    for (int i = 0; i < TM; i++) {
        int m = m0 + tr * TM + i;
        int b = m >> 11;                  // / 2048
        int t = m & 2047;
        float v0 = acc[i][0], v1 = acc[i][1], v2 = acc[i][2], v3 = acc[i][3];
        float o0, o1, o2, o3;
        if (sec < 2) {
            float ca = cosp[t * HD + d0];
            float sa = sinp[t * HD + d0];
            float cb = cosp[t * HD + d0 + 2];
            float sb = sinp[t * HD + d0 + 2];
            o0 = v0 * ca - v1 * sa;
            o1 = v1 * ca + v0 * sa;
            o2 = v2 * cb - v3 * sb;
            o3 = v3 * cb + v2 * sb;
        } else {
            o0 = v0; o1 = v1; o2 = v2; o3 = v3;
        }
        int off = ((b * NH + h) * TDIM + t) * HD + d0;
        dst[off + 0] = o0; dst[off + 1] = o1;
        dst[off + 2] = o2; dst[off + 3] = o3;
    }
}

// ---------------- Kernel 2: causal flash attention ----------------
// grid: (32 q-tiles, 32 bh). 256 threads (16x16), 4x4 microtiles.
// smem: Qs[64][64], Ks[64][65] (reused as P), Vs[64][65], red[64][16]
#define FA_SMEM ((64*64 + 2*64*65 + 64*16) * 4)

__global__ __launch_bounds__(256) void flash_kernel()
{
    extern __shared__ float sm[];
    float (*Qs)[64] = (float(*)[64])sm;
    float (*Ks)[65] = (float(*)[65])(sm + 64 * 64);
    float (*Vs)[65] = (float(*)[65])(sm + 64 * 64 + 64 * 65);
    float (*red)[16] = (float(*)[16])(sm + 64 * 64 + 2 * 64 * 65);

    const int qi = blockIdx.x;            // 0..31
    const int bh = blockIdx.y;            // 0..31
    const float* qb = g_q + (size_t)bh * TDIM * HD;
    const float* kb = g_k + (size_t)bh * TDIM * HD;
    const float* vb = g_v + (size_t)bh * TDIM * HD;
    const int tid = threadIdx.x;
    const int tr = tid >> 4, tc = tid & 15;

    #pragma unroll
    for (int i = 0; i < 16; i++) {
        int idx = tid + i * 256;
        int r = idx >> 6, c = idx & 63;
        Qs[r][c] = qb[(qi * 64 + r) * HD + c];
    }

    float m_i[4], l_i[4], acc[4][4];
    #pragma unroll
    for (int i = 0; i < 4; i++) {
        m_i[i] = -1e30f; l_i[i] = 0.f;
        #pragma unroll
        for (int j = 0; j < 4; j++) acc[i][j] = 0.f;
    }
    __syncthreads();

    for (int kt = 0; kt <= qi; kt++) {
        #pragma unroll
        for (int i = 0; i < 16; i++) {
            int idx = tid + i * 256;
            int r = idx >> 6, c = idx & 63;
            Ks[r][c] = kb[(kt * 64 + r) * HD + c];
            Vs[r][c] = vb[(kt * 64 + r) * HD + c];
        }
        __syncthreads();

        // S = Q K^T * scale, causal mask
        float s[4][4];
        #pragma unroll
        for (int i = 0; i < 4; i++)
            #pragma unroll
            for (int j = 0; j < 4; j++) s[i][j] = 0.f;
        #pragma unroll 8
        for (int kk = 0; kk < 64; kk++) {
            float a[4], b[4];
            #pragma unroll
            for (int i = 0; i < 4; i++) a[i] = Qs[tr * 4 + i][kk];
            #pragma unroll
            for (int j = 0; j < 4; j++) b[j] = Ks[tc * 4 + j][kk];
            #pragma unroll
            for (int i = 0; i < 4; i++)
                #pragma unroll
                for (int j = 0; j < 4; j++)
                    s[i][j] = fmaf(a[i], b[j], s[i][j]);
        }
        const float scale = 0.125f;       // 1/sqrt(64)
        #pragma unroll
        for (int i = 0; i < 4; i++) {
            int qrow = qi * 64 + tr * 4 + i;
            #pragma unroll
            for (int j = 0; j < 4; j++) {
                int kcol = kt * 64 + tc * 4 + j;
                s[i][j] = (kcol <= qrow) ? s[i][j] * scale : -1e30f;
            }
        }

        // row max partials
        float pm[4];
        #pragma unroll
        for (int i = 0; i < 4; i++) {
            pm[i] = fmaxf(fmaxf(s[i][0], s[i][1]), fmaxf(s[i][2], s[i][3]));
            red[tr * 4 + i][tc] = pm[i];
        }
        __syncthreads();      // also guarantees all Ks reads done (S loop precedes)
        float mnew[4], alpha[4];
        #pragma unroll
        for (int i = 0; i < 4; i++) {
            float rm = -1e30f;
            #pragma unroll
            for (int u = 0; u < 16; u++) rm = fmaxf(rm, red[tr * 4 + i][u]);
            mnew[i] = fmaxf(m_i[i], rm);
            alpha[i] = __expf(m_i[i] - mnew[i]);
        }
        __syncthreads();      // red reads done before reuse; Ks reuse as P safe

        // P = exp(s - mnew), write into Ks buffer; row-sum partials
        float ps[4] = {0.f, 0.f, 0.f, 0.f};
        #pragma unroll
        for (int i = 0; i < 4; i++) {
            #pragma unroll
            for (int j = 0; j < 4; j++) {
                float p = __expf(s[i][j] - mnew[i]);
                Ks[tr * 4 + i][tc * 4 + j] = p;
                ps[i] += p;
            }
            red[tr * 4 + i][tc] = ps[i];
        }
        __syncthreads();
        #pragma unroll
        for (int i = 0; i < 4; i++) {
            float rs = 0.f;
            #pragma unroll
            for (int u = 0; u < 16; u++) rs += red[tr * 4 + i][u];
            l_i[i] = l_i[i] * alpha[i] + rs;
            m_i[i] = mnew[i];
            #pragma unroll
            for (int j = 0; j < 4; j++) acc[i][j] *= alpha[i];
        }

        // O += P @ V  (P lives in Ks buffer)
        #pragma unroll 8
        for (int kk = 0; kk < 64; kk++) {
            float p[4], vv[4];
            #pragma unroll
            for (int i = 0; i < 4; i++) p[i] = Ks[tr * 4 + i][kk];
            #pragma unroll
            for (int j = 0; j < 4; j++) vv[j] = Vs[kk][tc * 4 + j];
            #pragma unroll
            for (int i = 0; i < 4; i++)
                #pragma unroll
                for (int j = 0; j < 4; j++)
                    acc[i][j] = fmaf(p[i], vv[j], acc[i][j]);
        }
        __syncthreads();      // before next tile overwrites Ks/Vs
    }

    // write y in [B,T,C] layout
    const int b = bh >> 4, h = bh & 15;
    #pragma unroll
    for (int i = 0; i < 4; i++) {
        int t = qi * 64 + tr * 4 + i;
        float inv = 1.0f / l_i[i];
        #pragma unroll
        for (int j = 0; j < 4; j++) {
            int d = tc * 4 + j;
            g_y[(b * TDIM + t) * CDIM + h * HD + d] = acc[i][j] * inv;
        }
    }
}

// ---------------- Kernel 3: output projection ----------------
__global__ __launch_bounds__(256) void proj_kernel(
    const float* __restrict__ W,      // [1024,1024]
    float* __restrict__ out)          // [4096,1024]
{
    __shared__ float As[BM][BK];
    __shared__ float Bs[BK][BN];
    const int tid = threadIdx.x;
    const int tr = tid >> 4;
    const int tc = tid & 15;
    const int m0 = blockIdx.y * BM;
    const int n0 = blockIdx.x * BN;

    float acc[TM][TN];
    #pragma unroll
    for (int i = 0; i < TM; i++)
        #pragma unroll
        for (int j = 0; j < TN; j++) acc[i][j] = 0.f;

    for (int k0 = 0; k0 < CDIM; k0 += BK) {
        #pragma unroll
        for (int i = 0; i < 8; i++) {
            int idx = tid + i * 256;
            int r = idx >> 4, c = idx & 15;
            As[r][c] = g_y[(m0 + r) * CDIM + k0 + c];
        }
        #pragma unroll
        for (int i = 0; i < 4; i++) {
            int idx = tid + i * 256;
            int r = idx >> 6, c = idx & 63;
            Bs[r][c] = W[(k0 + r) * CDIM + n0 + c];
        }
        __syncthreads();
        #pragma unroll
        for (int kk = 0; kk < BK; kk++) {
            float a[TM], b[TN];
            #pragma unroll
            for (int i = 0; i < TM; i++) a[i] = As[tr * TM + i][kk];
            #pragma unroll
            for (int j = 0; j < TN; j++) b[j] = Bs[kk][tc * TN + j];
            #pragma unroll
            for (int i = 0; i < TM; i++)
                #pragma unroll
                for (int j = 0; j < TN; j++)
                    acc[i][j] = fmaf(a[i], b[j], acc[i][j]);
        }
        __syncthreads();
    }
    #pragma unroll
    for (int i = 0; i < TM; i++) {
        int m = m0 + tr * TM + i;
        #pragma unroll
        for (int j = 0; j < TN; j++)
            out[m * CDIM + n0 + tc * TN + j] = acc[i][j];
    }
}

extern "C" void kernel_launch(void* const* d_in, const int* in_sizes, int n_in,
                              void* d_out, int out_size)
{
    const float* x     = (const float*)d_in[0];
    const float* sinp  = (const float*)d_in[1];
    const float* cosp  = (const float*)d_in[2];
    const float* Wqkv  = (const float*)d_in[3];
    const float* Wproj = (const float*)d_in[4];
    float* out = (float*)d_out;

    // idempotent, host-side, capture-safe
    cudaFuncSetAttribute(flash_kernel, cudaFuncAttributeMaxDynamicSharedMemorySize, FA_SMEM);

    qkv_rope_kernel<<<dim3(NQKV / BN, MDIM / BM), 256>>>(x, Wqkv, sinp, cosp);
    flash_kernel<<<dim3(TDIM / 64, BDIM * NH), 256, FA_SMEM>>>();
    proj_kernel<<<dim3(CDIM / BN, MDIM / BM), 256>>>(Wproj, out);
}

// round 5
// speedup vs baseline: 1.4927x; 1.4927x over previous
#include <cuda_runtime.h>
#include <cstdint>
#include <math.h>

#define BDIM 2
#define TDIM 2048
#define CDIM 1024
#define NH 16
#define HD 64
#define MDIM (BDIM*TDIM)   // 4096
#define NQKV (3*CDIM)      // 3072

// Scratch (allocation-free rule: __device__ globals)
__device__ float g_q[BDIM*NH*TDIM*HD];
__device__ float g_k[BDIM*NH*TDIM*HD];
__device__ float g_v[BDIM*NH*TDIM*HD];
__device__ float g_y[MDIM*CDIM];
__device__ float g_wt_qkv[NQKV*CDIM];   // W_qkv transposed [N][K], tf32-rounded
__device__ float g_wt_proj[CDIM*CDIM];  // W_proj transposed [N][K], tf32-rounded

__device__ __forceinline__ uint32_t cvt_tf32(float x) {
    uint32_t r; asm("cvt.rna.tf32.f32 %0, %1;" : "=r"(r) : "f"(x)); return r;
}
__device__ __forceinline__ void mma_tf32(float* d, const uint32_t* a, const uint32_t* b) {
    asm volatile(
        "mma.sync.aligned.m16n8k8.row.col.f32.tf32.tf32.f32 "
        "{%0,%1,%2,%3}, {%4,%5,%6,%7}, {%8,%9}, {%0,%1,%2,%3};"
        : "+f"(d[0]), "+f"(d[1]), "+f"(d[2]), "+f"(d[3])
        : "r"(a[0]), "r"(a[1]), "r"(a[2]), "r"(a[3]), "r"(b[0]), "r"(b[1]));
}

// ================= transpose + tf32 convert =================
__global__ __launch_bounds__(256) void transpose_cvt(
    const float* __restrict__ W, float* __restrict__ WT, int N)
{
    __shared__ float t[32][33];
    int n0 = blockIdx.x * 32, k0 = blockIdx.y * 32;
    int tx = threadIdx.x & 31, ty = threadIdx.x >> 5;
    #pragma unroll
    for (int i = 0; i < 4; i++)
        t[ty + i * 8][tx] = W[(size_t)(k0 + ty + i * 8) * N + n0 + tx];
    __syncthreads();
    #pragma unroll
    for (int i = 0; i < 4; i++)
        WT[(size_t)(n0 + ty + i * 8) * CDIM + k0 + tx] =
            __uint_as_float(cvt_tf32(t[tx][ty + i * 8]));
}

// ================= tf32 mma.sync GEMM (BM=128,BN=128,BK=16, 8 warps 2x4) =================
// warp tile 64x32: 4 m-tiles (16) x 4 n-tiles (8), k in 2 steps of 8.
// smem [row][20] padding -> conflict-free fragment LDS, 16B-aligned uint4 STS.

__device__ __forceinline__ void mma_mainloop(
    const float* __restrict__ Ap,   // row-major [*,1024] at tile row m0
    const float* __restrict__ Bp,   // row-major WT [*,1024] at tile row n0
    float (&acc)[4][4][4], int tid)
{
    __shared__ uint32_t As[2][128][20];
    __shared__ uint32_t Bs[2][128][20];
    const int lane = tid & 31, wid = tid >> 5;
    const int wm = wid >> 2, wn = wid & 3;
    const int lr = tid >> 2, lc4 = (tid & 3) * 4;      // global-load row, k-offset
    const int fr = lane >> 2, fc = lane & 3;           // fragment row/col within tile

    #pragma unroll
    for (int mt = 0; mt < 4; mt++)
        #pragma unroll
        for (int nt = 0; nt < 4; nt++)
            #pragma unroll
            for (int j = 0; j < 4; j++) acc[mt][nt][j] = 0.f;

    float4 av[2], bv[2];
    #pragma unroll
    for (int i = 0; i < 2; i++) {
        av[i] = *(const float4*)(Ap + (size_t)(lr + i * 64) * CDIM + lc4);
        bv[i] = *(const float4*)(Bp + (size_t)(lr + i * 64) * CDIM + lc4);
    }
    #pragma unroll
    for (int i = 0; i < 2; i++) {
        *(uint4*)&As[0][lr + i * 64][lc4] =
            make_uint4(cvt_tf32(av[i].x), cvt_tf32(av[i].y), cvt_tf32(av[i].z), cvt_tf32(av[i].w));
        *(uint4*)&Bs[0][lr + i * 64][lc4] =
            make_uint4(cvt_tf32(bv[i].x), cvt_tf32(bv[i].y), cvt_tf32(bv[i].z), cvt_tf32(bv[i].w));
    }
    __syncthreads();

    for (int it = 0; it < 64; it++) {
        const int cur = it & 1;
        if (it + 1 < 64) {
            const int k0 = (it + 1) * 16;
            #pragma unroll
            for (int i = 0; i < 2; i++) {
                av[i] = *(const float4*)(Ap + (size_t)(lr + i * 64) * CDIM + k0 + lc4);
                bv[i] = *(const float4*)(Bp + (size_t)(lr + i * 64) * CDIM + k0 + lc4);
            }
        }
        #pragma unroll
        for (int ks = 0; ks < 2; ks++) {
            const int c = ks * 8 + fc;
            uint32_t af[4][4];
            #pragma unroll
            for (int mt = 0; mt < 4; mt++) {
                const int r = wm * 64 + mt * 16 + fr;
                af[mt][0] = As[cur][r][c];
                af[mt][1] = As[cur][r + 8][c];
                af[mt][2] = As[cur][r][c + 4];
                af[mt][3] = As[cur][r + 8][c + 4];
            }
            uint32_t bf[4][2];
            #pragma unroll
            for (int nt = 0; nt < 4; nt++) {
                const int n = wn * 32 + nt * 8 + fr;
                bf[nt][0] = Bs[cur][n][c];
                bf[nt][1] = Bs[cur][n][c + 4];
            }
            #pragma unroll
            for (int mt = 0; mt < 4; mt++)
                #pragma unroll
                for (int nt = 0; nt < 4; nt++)
                    mma_tf32(acc[mt][nt], af[mt], bf[nt]);
        }
        if (it + 1 < 64) {
            #pragma unroll
            for (int i = 0; i < 2; i++) {
                *(uint4*)&As[cur ^ 1][lr + i * 64][lc4] =
                    make_uint4(cvt_tf32(av[i].x), cvt_tf32(av[i].y), cvt_tf32(av[i].z), cvt_tf32(av[i].w));
                *(uint4*)&Bs[cur ^ 1][lr + i * 64][lc4] =
                    make_uint4(cvt_tf32(bv[i].x), cvt_tf32(bv[i].y), cvt_tf32(bv[i].z), cvt_tf32(bv[i].w));
            }
        }
        __syncthreads();
    }
}

__global__ __launch_bounds__(256) void gemm_qkv_mma(
    const float* __restrict__ x,
    const float* __restrict__ sinp, const float* __restrict__ cosp)
{
    const int tid = threadIdx.x;
    const int m0 = blockIdx.y * 128, n0 = blockIdx.x * 128;
    float acc[4][4][4];
    mma_mainloop(x + (size_t)m0 * CDIM, g_wt_qkv + (size_t)n0 * CDIM, acc, tid);

    const int lane = tid & 31, wid = tid >> 5;
    const int wm = wid >> 2, wn = wid & 3;
    const int sec = n0 >> 10;                 // 0=q,1=k,2=v (uniform: BN=128 divides 1024)
    const int nb = n0 & 1023;
    float* dst = (sec == 0) ? g_q : (sec == 1 ? g_k : g_v);

    #pragma unroll
    for (int mt = 0; mt < 4; mt++) {
        #pragma unroll
        for (int nt = 0; nt < 4; nt++) {
            const int col = wn * 32 + nt * 8 + (lane & 3) * 2;
            const int nc = nb + col;
            const int h = nc >> 6, d = nc & 63;
            #pragma unroll
            for (int half = 0; half < 2; half++) {
                const int row = m0 + wm * 64 + mt * 16 + (lane >> 2) + half * 8;
                const int b = row >> 11, t = row & 2047;
                float v0 = acc[mt][nt][half * 2], v1 = acc[mt][nt][half * 2 + 1];
                float o0, o1;
                if (sec < 2) {
                    float ca = cosp[t * HD + d], sa = sinp[t * HD + d];
                    o0 = v0 * ca - v1 * sa;
                    o1 = v1 * ca + v0 * sa;
                } else { o0 = v0; o1 = v1; }
                *(float2*)(dst + ((((size_t)b * NH + h) * TDIM + t) * HD + d)) =
                    make_float2(o0, o1);
            }
        }
    }
}

__global__ __launch_bounds__(256) void gemm_proj_mma(float* __restrict__ out)
{
    const int tid = threadIdx.x;
    const int m0 = blockIdx.y * 128, n0 = blockIdx.x * 128;
    float acc[4][4][4];
    mma_mainloop(g_y + (size_t)m0 * CDIM, g_wt_proj + (size_t)n0 * CDIM, acc, tid);

    const int lane = tid & 31, wid = tid >> 5;
    const int wm = wid >> 2, wn = wid & 3;
    #pragma unroll
    for (int mt = 0; mt < 4; mt++) {
        #pragma unroll
        for (int nt = 0; nt < 4; nt++) {
            const int col = n0 + wn * 32 + nt * 8 + (lane & 3) * 2;
            #pragma unroll
            for (int half = 0; half < 2; half++) {
                const int row = m0 + wm * 64 + mt * 16 + (lane >> 2) + half * 8;
                *(float2*)(out + (size_t)row * CDIM + col) =
                    make_float2(acc[mt][nt][half * 2], acc[mt][nt][half * 2 + 1]);
            }
        }
    }
}

// ================= Kernel 2: causal flash attention (FFMA, unchanged) =================
#define FA_SMEM ((64*64 + 2*64*65 + 64*16) * 4)

__global__ __launch_bounds__(256) void flash_kernel()
{
    extern __shared__ float smf[];
    float (*Qs)[64] = (float(*)[64])smf;
    float (*Ks)[65] = (float(*)[65])(smf + 64 * 64);
    float (*Vs)[65] = (float(*)[65])(smf + 64 * 64 + 64 * 65);
    float (*red)[16] = (float(*)[16])(smf + 64 * 64 + 2 * 64 * 65);

    const int qi = blockIdx.x;
    const int bh = blockIdx.y;
    const float* qb = g_q + (size_t)bh * TDIM * HD;
    const float* kb = g_k + (size_t)bh * TDIM * HD;
    const float* vb = g_v + (size_t)bh * TDIM * HD;
    const int tid = threadIdx.x;
    const int tr = tid >> 4, tc = tid & 15;

    #pragma unroll
    for (int i = 0; i < 16; i++) {
        int idx = tid + i * 256;
        int r = idx >> 6, c = idx & 63;
        Qs[r][c] = qb[(qi * 64 + r) * HD + c];
    }

    float m_i[4], l_i[4], acc[4][4];
    #pragma unroll
    for (int i = 0; i < 4; i++) {
        m_i[i] = -1e30f; l_i[i] = 0.f;
        #pragma unroll
        for (int j = 0; j < 4; j++) acc[i][j] = 0.f;
    }
    __syncthreads();

    for (int kt = 0; kt <= qi; kt++) {
        #pragma unroll
        for (int i = 0; i < 16; i++) {
            int idx = tid + i * 256;
            int r = idx >> 6, c = idx & 63;
            Ks[r][c] = kb[(kt * 64 + r) * HD + c];
            Vs[r][c] = vb[(kt * 64 + r) * HD + c];
        }
        __syncthreads();

        float s[4][4];
        #pragma unroll
        for (int i = 0; i < 4; i++)
            #pragma unroll
            for (int j = 0; j < 4; j++) s[i][j] = 0.f;
        #pragma unroll 8
        for (int kk = 0; kk < 64; kk++) {
            float a[4], b[4];
            #pragma unroll
            for (int i = 0; i < 4; i++) a[i] = Qs[tr * 4 + i][kk];
            #pragma unroll
            for (int j = 0; j < 4; j++) b[j] = Ks[tc * 4 + j][kk];
            #pragma unroll
            for (int i = 0; i < 4; i++)
                #pragma unroll
                for (int j = 0; j < 4; j++)
                    s[i][j] = fmaf(a[i], b[j], s[i][j]);
        }
        const float scale = 0.125f;
        #pragma unroll
        for (int i = 0; i < 4; i++) {
            int qrow = qi * 64 + tr * 4 + i;
            #pragma unroll
            for (int j = 0; j < 4; j++) {
                int kcol = kt * 64 + tc * 4 + j;
                s[i][j] = (kcol <= qrow) ? s[i][j] * scale : -1e30f;
            }
        }

        float pm[4];
        #pragma unroll
        for (int i = 0; i < 4; i++) {
            pm[i] = fmaxf(fmaxf(s[i][0], s[i][1]), fmaxf(s[i][2], s[i][3]));
            red[tr * 4 + i][tc] = pm[i];
        }
        __syncthreads();
        float mnew[4], alpha[4];
        #pragma unroll
        for (int i = 0; i < 4; i++) {
            float rm = -1e30f;
            #pragma unroll
            for (int u = 0; u < 16; u++) rm = fmaxf(rm, red[tr * 4 + i][u]);
            mnew[i] = fmaxf(m_i[i], rm);
            alpha[i] = __expf(m_i[i] - mnew[i]);
        }
        __syncthreads();

        float ps[4] = {0.f, 0.f, 0.f, 0.f};
        #pragma unroll
        for (int i = 0; i < 4; i++) {
            #pragma unroll
            for (int j = 0; j < 4; j++) {
                float p = __expf(s[i][j] - mnew[i]);
                Ks[tr * 4 + i][tc * 4 + j] = p;
                ps[i] += p;
            }
            red[tr * 4 + i][tc] = ps[i];
        }
        __syncthreads();
        #pragma unroll
        for (int i = 0; i < 4; i++) {
            float rs = 0.f;
            #pragma unroll
            for (int u = 0; u < 16; u++) rs += red[tr * 4 + i][u];
            l_i[i] = l_i[i] * alpha[i] + rs;
            m_i[i] = mnew[i];
            #pragma unroll
            for (int j = 0; j < 4; j++) acc[i][j] *= alpha[i];
        }

        #pragma unroll 8
        for (int kk = 0; kk < 64; kk++) {
            float p[4], vv[4];
            #pragma unroll
            for (int i = 0; i < 4; i++) p[i] = Ks[tr * 4 + i][kk];
            #pragma unroll
            for (int j = 0; j < 4; j++) vv[j] = Vs[kk][tc * 4 + j];
            #pragma unroll
            for (int i = 0; i < 4; i++)
                #pragma unroll
                for (int j = 0; j < 4; j++)
                    acc[i][j] = fmaf(p[i], vv[j], acc[i][j]);
        }
        __syncthreads();
    }

    const int b = bh >> 4, h = bh & 15;
    #pragma unroll
    for (int i = 0; i < 4; i++) {
        int t = qi * 64 + tr * 4 + i;
        float inv = 1.0f / l_i[i];
        #pragma unroll
        for (int j = 0; j < 4; j++) {
            int d = tc * 4 + j;
            g_y[(b * TDIM + t) * CDIM + h * HD + d] = acc[i][j] * inv;
        }
    }
}

// ================= launch =================
extern "C" void kernel_launch(void* const* d_in, const int* in_sizes, int n_in,
                              void* d_out, int out_size)
{
    const float* x     = (const float*)d_in[0];
    const float* sinp  = (const float*)d_in[1];
    const float* cosp  = (const float*)d_in[2];
    const float* Wqkv  = (const float*)d_in[3];
    const float* Wproj = (const float*)d_in[4];
    float* out = (float*)d_out;

    float* wt_qkv;  cudaGetSymbolAddress((void**)&wt_qkv,  g_wt_qkv);
    float* wt_proj; cudaGetSymbolAddress((void**)&wt_proj, g_wt_proj);

    cudaFuncSetAttribute(flash_kernel, cudaFuncAttributeMaxDynamicSharedMemorySize, FA_SMEM);

    transpose_cvt<<<dim3(NQKV / 32, CDIM / 32), 256>>>(Wqkv,  wt_qkv,  NQKV);
    transpose_cvt<<<dim3(CDIM / 32, CDIM / 32), 256>>>(Wproj, wt_proj, CDIM);

    gemm_qkv_mma<<<dim3(NQKV / 128, MDIM / 128), 256>>>(x, sinp, cosp);
    flash_kernel<<<dim3(TDIM / 64, BDIM * NH), 256, FA_SMEM>>>();
    gemm_proj_mma<<<dim3(CDIM / 128, MDIM / 128), 256>>>(out);
}

// round 6
// speedup vs baseline: 2.7692x; 1.8552x over previous
#include <cuda_runtime.h>
#include <cstdint>
#include <math.h>

#define BDIM 2
#define TDIM 2048
#define CDIM 1024
#define NH 16
#define HD 64
#define MDIM (BDIM*TDIM)   // 4096
#define NQKV (3*CDIM)      // 3072

// Scratch (allocation-free rule: __device__ globals)
__device__ float g_q[BDIM*NH*TDIM*HD];
__device__ float g_k[BDIM*NH*TDIM*HD];
__device__ float g_v[BDIM*NH*TDIM*HD];
__device__ float g_y[MDIM*CDIM];
__device__ float g_wt_qkv[NQKV*CDIM];   // W_qkv transposed [N][K], tf32-rounded
__device__ float g_wt_proj[CDIM*CDIM];  // W_proj transposed [N][K], tf32-rounded

__device__ __forceinline__ uint32_t cvt_tf32(float x) {
    uint32_t r; asm("cvt.rna.tf32.f32 %0, %1;" : "=r"(r) : "f"(x)); return r;
}
__device__ __forceinline__ void mma_tf32(float* d, const uint32_t* a, const uint32_t* b) {
    asm volatile(
        "mma.sync.aligned.m16n8k8.row.col.f32.tf32.tf32.f32 "
        "{%0,%1,%2,%3}, {%4,%5,%6,%7}, {%8,%9}, {%0,%1,%2,%3};"
        : "+f"(d[0]), "+f"(d[1]), "+f"(d[2]), "+f"(d[3])
        : "r"(a[0]), "r"(a[1]), "r"(a[2]), "r"(a[3]), "r"(b[0]), "r"(b[1]));
}
__device__ __forceinline__ void cp16(uint32_t daddr, const void* g) {
    asm volatile("cp.async.cg.shared.global [%0], [%1], 16;" :: "r"(daddr), "l"(g) : "memory");
}

// ================= transpose + tf32 convert =================
__global__ __launch_bounds__(256) void transpose_cvt(
    const float* __restrict__ W, float* __restrict__ WT, int N)
{
    __shared__ float t[32][33];
    int n0 = blockIdx.x * 32, k0 = blockIdx.y * 32;
    int tx = threadIdx.x & 31, ty = threadIdx.x >> 5;
    #pragma unroll
    for (int i = 0; i < 4; i++)
        t[ty + i * 8][tx] = W[(size_t)(k0 + ty + i * 8) * N + n0 + tx];
    __syncthreads();
    #pragma unroll
    for (int i = 0; i < 4; i++)
        WT[(size_t)(n0 + ty + i * 8) * CDIM + k0 + tx] =
            __uint_as_float(cvt_tf32(t[tx][ty + i * 8]));
}

// ================= tf32 mma.sync GEMM (BM=128,BN=128,BK=16, 8 warps 2x4) =================
__device__ __forceinline__ void mma_mainloop(
    const float* __restrict__ Ap, const float* __restrict__ Bp,
    float (&acc)[4][4][4], int tid)
{
    __shared__ uint32_t As[2][128][20];
    __shared__ uint32_t Bs[2][128][20];
    const int lane = tid & 31, wid = tid >> 5;
    const int wm = wid >> 2, wn = wid & 3;
    const int lr = tid >> 2, lc4 = (tid & 3) * 4;
    const int fr = lane >> 2, fc = lane & 3;

    #pragma unroll
    for (int mt = 0; mt < 4; mt++)
        #pragma unroll
        for (int nt = 0; nt < 4; nt++)
            #pragma unroll
            for (int j = 0; j < 4; j++) acc[mt][nt][j] = 0.f;

    float4 av[2], bv[2];
    #pragma unroll
    for (int i = 0; i < 2; i++) {
        av[i] = *(const float4*)(Ap + (size_t)(lr + i * 64) * CDIM + lc4);
        bv[i] = *(const float4*)(Bp + (size_t)(lr + i * 64) * CDIM + lc4);
    }
    #pragma unroll
    for (int i = 0; i < 2; i++) {
        *(uint4*)&As[0][lr + i * 64][lc4] =
            make_uint4(cvt_tf32(av[i].x), cvt_tf32(av[i].y), cvt_tf32(av[i].z), cvt_tf32(av[i].w));
        *(uint4*)&Bs[0][lr + i * 64][lc4] =
            make_uint4(cvt_tf32(bv[i].x), cvt_tf32(bv[i].y), cvt_tf32(bv[i].z), cvt_tf32(bv[i].w));
    }
    __syncthreads();

    for (int it = 0; it < 64; it++) {
        const int cur = it & 1;
        if (it + 1 < 64) {
            const int k0 = (it + 1) * 16;
            #pragma unroll
            for (int i = 0; i < 2; i++) {
                av[i] = *(const float4*)(Ap + (size_t)(lr + i * 64) * CDIM + k0 + lc4);
                bv[i] = *(const float4*)(Bp + (size_t)(lr + i * 64) * CDIM + k0 + lc4);
            }
        }
        #pragma unroll
        for (int ks = 0; ks < 2; ks++) {
            const int c = ks * 8 + fc;
            uint32_t af[4][4];
            #pragma unroll
            for (int mt = 0; mt < 4; mt++) {
                const int r = wm * 64 + mt * 16 + fr;
                af[mt][0] = As[cur][r][c];
                af[mt][1] = As[cur][r + 8][c];
                af[mt][2] = As[cur][r][c + 4];
                af[mt][3] = As[cur][r + 8][c + 4];
            }
            uint32_t bf[4][2];
            #pragma unroll
            for (int nt = 0; nt < 4; nt++) {
                const int n = wn * 32 + nt * 8 + fr;
                bf[nt][0] = Bs[cur][n][c];
                bf[nt][1] = Bs[cur][n][c + 4];
            }
            #pragma unroll
            for (int mt = 0; mt < 4; mt++)
                #pragma unroll
                for (int nt = 0; nt < 4; nt++)
                    mma_tf32(acc[mt][nt], af[mt], bf[nt]);
        }
        if (it + 1 < 64) {
            #pragma unroll
            for (int i = 0; i < 2; i++) {
                *(uint4*)&As[cur ^ 1][lr + i * 64][lc4] =
                    make_uint4(cvt_tf32(av[i].x), cvt_tf32(av[i].y), cvt_tf32(av[i].z), cvt_tf32(av[i].w));
                *(uint4*)&Bs[cur ^ 1][lr + i * 64][lc4] =
                    make_uint4(cvt_tf32(bv[i].x), cvt_tf32(bv[i].y), cvt_tf32(bv[i].z), cvt_tf32(bv[i].w));
            }
        }
        __syncthreads();
    }
}

__global__ __launch_bounds__(256) void gemm_qkv_mma(
    const float* __restrict__ x,
    const float* __restrict__ sinp, const float* __restrict__ cosp)
{
    const int tid = threadIdx.x;
    const int m0 = blockIdx.y * 128, n0 = blockIdx.x * 128;
    float acc[4][4][4];
    mma_mainloop(x + (size_t)m0 * CDIM, g_wt_qkv + (size_t)n0 * CDIM, acc, tid);

    const int lane = tid & 31, wid = tid >> 5;
    const int wm = wid >> 2, wn = wid & 3;
    const int sec = n0 >> 10;
    const int nb = n0 & 1023;
    float* dst = (sec == 0) ? g_q : (sec == 1 ? g_k : g_v);

    #pragma unroll
    for (int mt = 0; mt < 4; mt++) {
        #pragma unroll
        for (int nt = 0; nt < 4; nt++) {
            const int col = wn * 32 + nt * 8 + (lane & 3) * 2;
            const int nc = nb + col;
            const int h = nc >> 6, d = nc & 63;
            #pragma unroll
            for (int half = 0; half < 2; half++) {
                const int row = m0 + wm * 64 + mt * 16 + (lane >> 2) + half * 8;
                const int b = row >> 11, t = row & 2047;
                float v0 = acc[mt][nt][half * 2], v1 = acc[mt][nt][half * 2 + 1];
                float o0, o1;
                if (sec < 2) {
                    float ca = cosp[t * HD + d], sa = sinp[t * HD + d];
                    o0 = v0 * ca - v1 * sa;
                    o1 = v1 * ca + v0 * sa;
                } else { o0 = v0; o1 = v1; }
                // round to tf32 here: flash consumes these as tf32 mma operands
                *(float2*)(dst + ((((size_t)b * NH + h) * TDIM + t) * HD + d)) =
                    make_float2(__uint_as_float(cvt_tf32(o0)), __uint_as_float(cvt_tf32(o1)));
            }
        }
    }
}

__global__ __launch_bounds__(256) void gemm_proj_mma(float* __restrict__ out)
{
    const int tid = threadIdx.x;
    const int m0 = blockIdx.y * 128, n0 = blockIdx.x * 128;
    float acc[4][4][4];
    mma_mainloop(g_y + (size_t)m0 * CDIM, g_wt_proj + (size_t)n0 * CDIM, acc, tid);

    const int lane = tid & 31, wid = tid >> 5;
    const int wm = wid >> 2, wn = wid & 3;
    #pragma unroll
    for (int mt = 0; mt < 4; mt++) {
        #pragma unroll
        for (int nt = 0; nt < 4; nt++) {
            const int col = n0 + wn * 32 + nt * 8 + (lane & 3) * 2;
            #pragma unroll
            for (int half = 0; half < 2; half++) {
                const int row = m0 + wm * 64 + mt * 16 + (lane >> 2) + half * 8;
                *(float2*)(out + (size_t)row * CDIM + col) =
                    make_float2(acc[mt][nt][half * 2], acc[mt][nt][half * 2 + 1]);
            }
        }
    }
}

// ================= flash attention on mma.sync tf32 =================
// CTA: 64 q-rows, 4 warps (warp = 16 q x 64 k). BK=64, cp.async double buffer.
// smem floats: Qs[64][68] @0, Ps[64][68] @4352, Ks[2][64][68] @8704, Vs[2][64][72] @17408
#define FA_SMEM 106496

__global__ __launch_bounds__(128) void flash_mma()
{
    extern __shared__ float sm[];
    float* Qs = sm;                 // [64][68]
    float* Ps = sm + 4352;          // [64][68]
    float* KsB = sm + 8704;         // [2][64][68]
    float* VsB = sm + 17408;        // [2][64][72]

    const int bh = blockIdx.x;
    const int qt = 31 - blockIdx.y;         // long CTAs first
    const int q0 = qt * 64;
    const int tid = threadIdx.x;
    const int lane = tid & 31, wid = tid >> 5;
    const int fr = lane >> 2, fc = lane & 3;
    const int wq = wid * 16;

    const float* qb = g_q + (size_t)bh * TDIM * HD;
    const float* kb = g_k + (size_t)bh * TDIM * HD;
    const float* vb = g_v + (size_t)bh * TDIM * HD;

    // Q tile (already tf32-rounded by qkv epilogue)
    #pragma unroll
    for (int i = 0; i < 8; i++) {
        int lin = tid + i * 128;
        int r = lin >> 4, c4 = (lin & 15) * 4;
        *(float4*)(Qs + r * 68 + c4) = *(const float4*)(qb + (size_t)(q0 + r) * HD + c4);
    }
    // issue K/V tile 0 into buf 0
    #pragma unroll
    for (int i = 0; i < 8; i++) {
        int lin = tid + i * 128;
        int r = lin >> 4, c4 = (lin & 15) * 4;
        cp16((uint32_t)__cvta_generic_to_shared(KsB + r * 68 + c4),
             kb + (size_t)r * HD + c4);
        cp16((uint32_t)__cvta_generic_to_shared(VsB + r * 72 + c4),
             vb + (size_t)r * HD + c4);
    }
    asm volatile("cp.async.commit_group;" ::: "memory");

    float o[8][4];
    #pragma unroll
    for (int nt = 0; nt < 8; nt++)
        #pragma unroll
        for (int j = 0; j < 4; j++) o[nt][j] = 0.f;
    float m0 = -1e30f, m1 = -1e30f, l0 = 0.f, l1 = 0.f;

    for (int kt = 0; kt <= qt; kt++) {
        const int buf = kt & 1;
        if (kt < qt) {
            const int kr = (kt + 1) * 64;
            float* Kn = KsB + (buf ^ 1) * 4352;
            float* Vn = VsB + (buf ^ 1) * 4608;
            #pragma unroll
            for (int i = 0; i < 8; i++) {
                int lin = tid + i * 128;
                int r = lin >> 4, c4 = (lin & 15) * 4;
                cp16((uint32_t)__cvta_generic_to_shared(Kn + r * 68 + c4),
                     kb + (size_t)(kr + r) * HD + c4);
                cp16((uint32_t)__cvta_generic_to_shared(Vn + r * 72 + c4),
                     vb + (size_t)(kr + r) * HD + c4);
            }
            asm volatile("cp.async.commit_group;" ::: "memory");
            asm volatile("cp.async.wait_group 1;" ::: "memory");
        } else {
            asm volatile("cp.async.wait_group 0;" ::: "memory");
        }
        __syncthreads();

        const float* Kb = KsB + buf * 4352;
        const float* Vb = VsB + buf * 4608;

        // ---- S = Q K^T ----
        float s[8][4];
        #pragma unroll
        for (int nt = 0; nt < 8; nt++)
            #pragma unroll
            for (int j = 0; j < 4; j++) s[nt][j] = 0.f;
        #pragma unroll
        for (int ks = 0; ks < 8; ks++) {
            const int c = ks * 8 + fc;
            uint32_t a[4];
            a[0] = __float_as_uint(Qs[(wq + fr) * 68 + c]);
            a[1] = __float_as_uint(Qs[(wq + fr + 8) * 68 + c]);
            a[2] = __float_as_uint(Qs[(wq + fr) * 68 + c + 4]);
            a[3] = __float_as_uint(Qs[(wq + fr + 8) * 68 + c + 4]);
            #pragma unroll
            for (int nt = 0; nt < 8; nt++) {
                uint32_t b[2];
                b[0] = __float_as_uint(Kb[(nt * 8 + fr) * 68 + c]);
                b[1] = __float_as_uint(Kb[(nt * 8 + fr) * 68 + c + 4]);
                mma_tf32(s[nt], a, b);
            }
        }
        #pragma unroll
        for (int nt = 0; nt < 8; nt++)
            #pragma unroll
            for (int j = 0; j < 4; j++) s[nt][j] *= 0.125f;

        if (kt == qt) {            // diagonal tile: causal mask (local coords)
            const int r0 = wq + fr, r1 = r0 + 8;
            #pragma unroll
            for (int nt = 0; nt < 8; nt++) {
                const int cl = nt * 8 + 2 * fc;
                if (cl > r0)     s[nt][0] = -1e30f;
                if (cl + 1 > r0) s[nt][1] = -1e30f;
                if (cl > r1)     s[nt][2] = -1e30f;
                if (cl + 1 > r1) s[nt][3] = -1e30f;
            }
        }

        // ---- online softmax (warp-local: quad shuffles) ----
        float mx0 = -1e30f, mx1 = -1e30f;
        #pragma unroll
        for (int nt = 0; nt < 8; nt++) {
            mx0 = fmaxf(mx0, fmaxf(s[nt][0], s[nt][1]));
            mx1 = fmaxf(mx1, fmaxf(s[nt][2], s[nt][3]));
        }
        mx0 = fmaxf(mx0, __shfl_xor_sync(0xffffffffu, mx0, 1));
        mx0 = fmaxf(mx0, __shfl_xor_sync(0xffffffffu, mx0, 2));
        mx1 = fmaxf(mx1, __shfl_xor_sync(0xffffffffu, mx1, 1));
        mx1 = fmaxf(mx1, __shfl_xor_sync(0xffffffffu, mx1, 2));
        const float mn0 = fmaxf(m0, mx0), mn1 = fmaxf(m1, mx1);
        const float al0 = __expf(m0 - mn0), al1 = __expf(m1 - mn1);
        m0 = mn0; m1 = mn1;

        float ps0 = 0.f, ps1 = 0.f;
        #pragma unroll
        for (int nt = 0; nt < 8; nt++) {
            float p0 = __expf(s[nt][0] - mn0);
            float p1 = __expf(s[nt][1] - mn0);
            float p2 = __expf(s[nt][2] - mn1);
            float p3 = __expf(s[nt][3] - mn1);
            ps0 += p0 + p1; ps1 += p2 + p3;
            const int cl = nt * 8 + 2 * fc;
            Ps[(wq + fr) * 68 + cl]     = p0;
            Ps[(wq + fr) * 68 + cl + 1] = p1;
            Ps[(wq + fr + 8) * 68 + cl]     = p2;
            Ps[(wq + fr + 8) * 68 + cl + 1] = p3;
        }
        ps0 += __shfl_xor_sync(0xffffffffu, ps0, 1);
        ps0 += __shfl_xor_sync(0xffffffffu, ps0, 2);
        ps1 += __shfl_xor_sync(0xffffffffu, ps1, 1);
        ps1 += __shfl_xor_sync(0xffffffffu, ps1, 2);
        l0 = l0 * al0 + ps0;
        l1 = l1 * al1 + ps1;
        #pragma unroll
        for (int nt = 0; nt < 8; nt++) {
            o[nt][0] *= al0; o[nt][1] *= al0;
            o[nt][2] *= al1; o[nt][3] *= al1;
        }
        __syncwarp();

        // ---- O += P V   (B reads raw Vs[j][d] with swapped indices; pad 72 = conflict-free) ----
        #pragma unroll
        for (int ks = 0; ks < 8; ks++) {
            const int c = ks * 8 + fc;
            uint32_t a[4];
            a[0] = __float_as_uint(Ps[(wq + fr) * 68 + c]);
            a[1] = __float_as_uint(Ps[(wq + fr + 8) * 68 + c]);
            a[2] = __float_as_uint(Ps[(wq + fr) * 68 + c + 4]);
            a[3] = __float_as_uint(Ps[(wq + fr + 8) * 68 + c + 4]);
            #pragma unroll
            for (int nt = 0; nt < 8; nt++) {
                uint32_t b[2];
                b[0] = __float_as_uint(Vb[c * 72 + nt * 8 + fr]);
                b[1] = __float_as_uint(Vb[(c + 4) * 72 + nt * 8 + fr]);
                mma_tf32(o[nt], a, b);
            }
        }
        __syncthreads();   // all reads of Ks/Vs[buf] done before next iter's cp.async reuses it
    }

    // ---- epilogue: O/l -> g_y [B,T,C] ----
    const float inv0 = 1.0f / l0, inv1 = 1.0f / l1;
    const int b = bh >> 4, h = bh & 15;
    const int t0 = q0 + wq + fr, t1 = t0 + 8;
    #pragma unroll
    for (int nt = 0; nt < 8; nt++) {
        const int d = nt * 8 + 2 * fc;
        *(float2*)(g_y + (size_t)(b * TDIM + t0) * CDIM + h * HD + d) =
            make_float2(o[nt][0] * inv0, o[nt][1] * inv0);
        *(float2*)(g_y + (size_t)(b * TDIM + t1) * CDIM + h * HD + d) =
            make_float2(o[nt][2] * inv1, o[nt][3] * inv1);
    }
}

// ================= launch =================
extern "C" void kernel_launch(void* const* d_in, const int* in_sizes, int n_in,
                              void* d_out, int out_size)
{
    const float* x     = (const float*)d_in[0];
    const float* sinp  = (const float*)d_in[1];
    const float* cosp  = (const float*)d_in[2];
    const float* Wqkv  = (const float*)d_in[3];
    const float* Wproj = (const float*)d_in[4];
    float* out = (float*)d_out;

    float* wt_qkv;  cudaGetSymbolAddress((void**)&wt_qkv,  g_wt_qkv);
    float* wt_proj; cudaGetSymbolAddress((void**)&wt_proj, g_wt_proj);

    cudaFuncSetAttribute(flash_mma, cudaFuncAttributeMaxDynamicSharedMemorySize, FA_SMEM);

    transpose_cvt<<<dim3(NQKV / 32, CDIM / 32), 256>>>(Wqkv,  wt_qkv,  NQKV);
    transpose_cvt<<<dim3(CDIM / 32, CDIM / 32), 256>>>(Wproj, wt_proj, CDIM);

    gemm_qkv_mma<<<dim3(NQKV / 128, MDIM / 128), 256>>>(x, sinp, cosp);
    flash_mma<<<dim3(BDIM * NH, TDIM / 64), 128, FA_SMEM>>>();
    gemm_proj_mma<<<dim3(CDIM / 128, MDIM / 128), 256>>>(out);
}

// round 7
// speedup vs baseline: 3.2134x; 1.1604x over previous
#include <cuda_runtime.h>
#include <cstdint>
#include <math.h>

#define BDIM 2
#define TDIM 2048
#define CDIM 1024
#define NH 16
#define HD 64
#define MDIM (BDIM*TDIM)   // 4096
#define NQKV (3*CDIM)      // 3072

// Scratch (allocation-free rule: __device__ globals)
__device__ float g_q[BDIM*NH*TDIM*HD];
__device__ float g_k[BDIM*NH*TDIM*HD];
__device__ float g_v[BDIM*NH*TDIM*HD];
__device__ float g_y[MDIM*CDIM];          // tf32-rounded by flash epilogue
__device__ float g_x32[MDIM*CDIM];        // x, tf32-rounded
__device__ float g_wt_qkv[NQKV*CDIM];     // W_qkv^T [N][K], tf32-rounded
__device__ float g_wt_proj[CDIM*CDIM];    // W_proj^T [N][K], tf32-rounded

__device__ __forceinline__ uint32_t cvt_tf32(float x) {
    uint32_t r; asm("cvt.rna.tf32.f32 %0, %1;" : "=r"(r) : "f"(x)); return r;
}
__device__ __forceinline__ void mma_tf32(float* d, const uint32_t* a, const uint32_t* b) {
    asm volatile(
        "mma.sync.aligned.m16n8k8.row.col.f32.tf32.tf32.f32 "
        "{%0,%1,%2,%3}, {%4,%5,%6,%7}, {%8,%9}, {%0,%1,%2,%3};"
        : "+f"(d[0]), "+f"(d[1]), "+f"(d[2]), "+f"(d[3])
        : "r"(a[0]), "r"(a[1]), "r"(a[2]), "r"(a[3]), "r"(b[0]), "r"(b[1]));
}
__device__ __forceinline__ void cp16(uint32_t daddr, const void* g) {
    asm volatile("cp.async.cg.shared.global [%0], [%1], 16;" :: "r"(daddr), "l"(g) : "memory");
}

// ================= pre-round x to tf32 =================
__global__ __launch_bounds__(256) void cvt_x32_kernel(const float* __restrict__ x)
{
    int i = blockIdx.x * 256 + threadIdx.x;        // over float4s (1M)
    float4 v = ((const float4*)x)[i];
    ((uint4*)g_x32)[i] = make_uint4(cvt_tf32(v.x), cvt_tf32(v.y), cvt_tf32(v.z), cvt_tf32(v.w));
}

// ================= transpose + tf32 convert =================
__global__ __launch_bounds__(256) void transpose_cvt(
    const float* __restrict__ W, float* __restrict__ WT, int N)
{
    __shared__ float t[32][33];
    int n0 = blockIdx.x * 32, k0 = blockIdx.y * 32;
    int tx = threadIdx.x & 31, ty = threadIdx.x >> 5;
    #pragma unroll
    for (int i = 0; i < 4; i++)
        t[ty + i * 8][tx] = W[(size_t)(k0 + ty + i * 8) * N + n0 + tx];
    __syncthreads();
    #pragma unroll
    for (int i = 0; i < 4; i++)
        WT[(size_t)(n0 + ty + i * 8) * CDIM + k0 + tx] =
            __uint_as_float(cvt_tf32(t[tx][ty + i * 8]));
}

// ================= tf32 mma.sync GEMM, 3-stage cp.async pipeline =================
// BM=BN=128, BK=16, 8 warps (2x4), warp tile 64x32. smem [row][20] pad.
#define GPITCH (128*20)
#define GSMEM (6*GPITCH*4)     // 3 stages x (A+B) = 61440 B

__device__ __forceinline__ void gemm_issue(
    uint32_t* As, uint32_t* Bs, const float* Ap, const float* Bp,
    int stage, int k0, int lr, int lc4)
{
    #pragma unroll
    for (int i = 0; i < 2; i++) {
        const int r = lr + i * 64;
        cp16((uint32_t)__cvta_generic_to_shared(As + stage * GPITCH + r * 20 + lc4),
             Ap + (size_t)r * CDIM + k0 + lc4);
        cp16((uint32_t)__cvta_generic_to_shared(Bs + stage * GPITCH + r * 20 + lc4),
             Bp + (size_t)r * CDIM + k0 + lc4);
    }
    asm volatile("cp.async.commit_group;" ::: "memory");
}

__device__ __forceinline__ void mma_mainloop(
    const float* __restrict__ Ap, const float* __restrict__ Bp,
    float (&acc)[4][4][4], int tid, uint32_t* smem)
{
    uint32_t* As = smem;               // [3][128][20]
    uint32_t* Bs = smem + 3 * GPITCH;
    const int lane = tid & 31, wid = tid >> 5;
    const int wm = wid >> 2, wn = wid & 3;
    const int lr = tid >> 2, lc4 = (tid & 3) * 4;
    const int fr = lane >> 2, fc = lane & 3;

    #pragma unroll
    for (int mt = 0; mt < 4; mt++)
        #pragma unroll
        for (int nt = 0; nt < 4; nt++)
            #pragma unroll
            for (int j = 0; j < 4; j++) acc[mt][nt][j] = 0.f;

    gemm_issue(As, Bs, Ap, Bp, 0, 0, lr, lc4);
    gemm_issue(As, Bs, Ap, Bp, 1, 16, lr, lc4);

    for (int it = 0; it < 64; it++) {
        const int cur = it - (it / 3) * 3;        // it % 3
        if (it < 63) asm volatile("cp.async.wait_group 1;" ::: "memory");
        else         asm volatile("cp.async.wait_group 0;" ::: "memory");
        __syncthreads();
        if (it + 2 < 64)
            gemm_issue(As, Bs, Ap, Bp, (it + 2) - ((it + 2) / 3) * 3, (it + 2) * 16, lr, lc4);

        const uint32_t* Ac = As + cur * GPITCH;
        const uint32_t* Bc = Bs + cur * GPITCH;
        #pragma unroll
        for (int ks = 0; ks < 2; ks++) {
            const int c = ks * 8 + fc;
            uint32_t af[4][4];
            #pragma unroll
            for (int mt = 0; mt < 4; mt++) {
                const int r = wm * 64 + mt * 16 + fr;
                af[mt][0] = Ac[r * 20 + c];
                af[mt][1] = Ac[(r + 8) * 20 + c];
                af[mt][2] = Ac[r * 20 + c + 4];
                af[mt][3] = Ac[(r + 8) * 20 + c + 4];
            }
            uint32_t bf[4][2];
            #pragma unroll
            for (int nt = 0; nt < 4; nt++) {
                const int n = wn * 32 + nt * 8 + fr;
                bf[nt][0] = Bc[n * 20 + c];
                bf[nt][1] = Bc[n * 20 + c + 4];
            }
            #pragma unroll
            for (int mt = 0; mt < 4; mt++)
                #pragma unroll
                for (int nt = 0; nt < 4; nt++)
                    mma_tf32(acc[mt][nt], af[mt], bf[nt]);
        }
        __syncthreads();
    }
}

__global__ __launch_bounds__(256) void gemm_qkv_mma(
    const float* __restrict__ sinp, const float* __restrict__ cosp)
{
    extern __shared__ uint32_t smu[];
    const int tid = threadIdx.x;
    const int m0 = blockIdx.y * 128, n0 = blockIdx.x * 128;
    float acc[4][4][4];
    mma_mainloop(g_x32 + (size_t)m0 * CDIM, g_wt_qkv + (size_t)n0 * CDIM, acc, tid, smu);

    const int lane = tid & 31, wid = tid >> 5;
    const int wm = wid >> 2, wn = wid & 3;
    const int sec = n0 >> 10;
    const int nb = n0 & 1023;
    float* dst = (sec == 0) ? g_q : (sec == 1 ? g_k : g_v);

    #pragma unroll
    for (int mt = 0; mt < 4; mt++) {
        #pragma unroll
        for (int nt = 0; nt < 4; nt++) {
            const int col = wn * 32 + nt * 8 + (lane & 3) * 2;
            const int nc = nb + col;
            const int h = nc >> 6, d = nc & 63;
            #pragma unroll
            for (int half = 0; half < 2; half++) {
                const int row = m0 + wm * 64 + mt * 16 + (lane >> 2) + half * 8;
                const int b = row >> 11, t = row & 2047;
                float v0 = acc[mt][nt][half * 2], v1 = acc[mt][nt][half * 2 + 1];
                float o0, o1;
                if (sec < 2) {
                    float ca = cosp[t * HD + d], sa = sinp[t * HD + d];
                    o0 = v0 * ca - v1 * sa;
                    o1 = v1 * ca + v0 * sa;
                } else { o0 = v0; o1 = v1; }
                // round to tf32 here: flash consumes these as tf32 mma operands
                *(float2*)(dst + ((((size_t)b * NH + h) * TDIM + t) * HD + d)) =
                    make_float2(__uint_as_float(cvt_tf32(o0)), __uint_as_float(cvt_tf32(o1)));
            }
        }
    }
}

__global__ __launch_bounds__(256) void gemm_proj_mma(float* __restrict__ out)
{
    extern __shared__ uint32_t smu[];
    const int tid = threadIdx.x;
    const int m0 = blockIdx.y * 128, n0 = blockIdx.x * 128;
    float acc[4][4][4];
    mma_mainloop(g_y + (size_t)m0 * CDIM, g_wt_proj + (size_t)n0 * CDIM, acc, tid, smu);

    const int lane = tid & 31, wid = tid >> 5;
    const int wm = wid >> 2, wn = wid & 3;
    #pragma unroll
    for (int mt = 0; mt < 4; mt++) {
        #pragma unroll
        for (int nt = 0; nt < 4; nt++) {
            const int col = n0 + wn * 32 + nt * 8 + (lane & 3) * 2;
            #pragma unroll
            for (int half = 0; half < 2; half++) {
                const int row = m0 + wm * 64 + mt * 16 + (lane >> 2) + half * 8;
                *(float2*)(out + (size_t)row * CDIM + col) =
                    make_float2(acc[mt][nt][half * 2], acc[mt][nt][half * 2 + 1]);
            }
        }
    }
}

// ================= flash attention on mma.sync tf32 =================
// CTA: 64 q-rows, 4 warps (warp = 16 q x 64 k). BK=64, cp.async double buffer.
#define FA_SMEM 106496

__global__ __launch_bounds__(128) void flash_mma()
{
    extern __shared__ float sm[];
    float* Qs = sm;                 // [64][68]
    float* Ps = sm + 4352;          // [64][68]
    float* KsB = sm + 8704;         // [2][64][68]
    float* VsB = sm + 17408;        // [2][64][72]

    const int bh = blockIdx.x;
    const int qt = 31 - blockIdx.y;         // long CTAs first
    const int q0 = qt * 64;
    const int tid = threadIdx.x;
    const int lane = tid & 31, wid = tid >> 5;
    const int fr = lane >> 2, fc = lane & 3;
    const int wq = wid * 16;

    const float* qb = g_q + (size_t)bh * TDIM * HD;
    const float* kb = g_k + (size_t)bh * TDIM * HD;
    const float* vb = g_v + (size_t)bh * TDIM * HD;

    #pragma unroll
    for (int i = 0; i < 8; i++) {
        int lin = tid + i * 128;
        int r = lin >> 4, c4 = (lin & 15) * 4;
        *(float4*)(Qs + r * 68 + c4) = *(const float4*)(qb + (size_t)(q0 + r) * HD + c4);
    }
    #pragma unroll
    for (int i = 0; i < 8; i++) {
        int lin = tid + i * 128;
        int r = lin >> 4, c4 = (lin & 15) * 4;
        cp16((uint32_t)__cvta_generic_to_shared(KsB + r * 68 + c4),
             kb + (size_t)r * HD + c4);
        cp16((uint32_t)__cvta_generic_to_shared(VsB + r * 72 + c4),
             vb + (size_t)r * HD + c4);
    }
    asm volatile("cp.async.commit_group;" ::: "memory");

    float o[8][4];
    #pragma unroll
    for (int nt = 0; nt < 8; nt++)
        #pragma unroll
        for (int j = 0; j < 4; j++) o[nt][j] = 0.f;
    float m0 = -1e30f, m1 = -1e30f, l0 = 0.f, l1 = 0.f;

    for (int kt = 0; kt <= qt; kt++) {
        const int buf = kt & 1;
        if (kt < qt) {
            const int kr = (kt + 1) * 64;
            float* Kn = KsB + (buf ^ 1) * 4352;
            float* Vn = VsB + (buf ^ 1) * 4608;
            #pragma unroll
            for (int i = 0; i < 8; i++) {
                int lin = tid + i * 128;
                int r = lin >> 4, c4 = (lin & 15) * 4;
                cp16((uint32_t)__cvta_generic_to_shared(Kn + r * 68 + c4),
                     kb + (size_t)(kr + r) * HD + c4);
                cp16((uint32_t)__cvta_generic_to_shared(Vn + r * 72 + c4),
                     vb + (size_t)(kr + r) * HD + c4);
            }
            asm volatile("cp.async.commit_group;" ::: "memory");
            asm volatile("cp.async.wait_group 1;" ::: "memory");
        } else {
            asm volatile("cp.async.wait_group 0;" ::: "memory");
        }
        __syncthreads();

        const float* Kb = KsB + buf * 4352;
        const float* Vb = VsB + buf * 4608;

        // ---- S = Q K^T ----
        float s[8][4];
        #pragma unroll
        for (int nt = 0; nt < 8; nt++)
            #pragma unroll
            for (int j = 0; j < 4; j++) s[nt][j] = 0.f;
        #pragma unroll
        for (int ks = 0; ks < 8; ks++) {
            const int c = ks * 8 + fc;
            uint32_t a[4];
            a[0] = __float_as_uint(Qs[(wq + fr) * 68 + c]);
            a[1] = __float_as_uint(Qs[(wq + fr + 8) * 68 + c]);
            a[2] = __float_as_uint(Qs[(wq + fr) * 68 + c + 4]);
            a[3] = __float_as_uint(Qs[(wq + fr + 8) * 68 + c + 4]);
            #pragma unroll
            for (int nt = 0; nt < 8; nt++) {
                uint32_t b[2];
                b[0] = __float_as_uint(Kb[(nt * 8 + fr) * 68 + c]);
                b[1] = __float_as_uint(Kb[(nt * 8 + fr) * 68 + c + 4]);
                mma_tf32(s[nt], a, b);
            }
        }
        #pragma unroll
        for (int nt = 0; nt < 8; nt++)
            #pragma unroll
            for (int j = 0; j < 4; j++) s[nt][j] *= 0.125f;

        if (kt == qt) {
            const int r0 = wq + fr, r1 = r0 + 8;
            #pragma unroll
            for (int nt = 0; nt < 8; nt++) {
                const int cl = nt * 8 + 2 * fc;
                if (cl > r0)     s[nt][0] = -1e30f;
                if (cl + 1 > r0) s[nt][1] = -1e30f;
                if (cl > r1)     s[nt][2] = -1e30f;
                if (cl + 1 > r1) s[nt][3] = -1e30f;
            }
        }

        // ---- online softmax (warp-local quad shuffles) ----
        float mx0 = -1e30f, mx1 = -1e30f;
        #pragma unroll
        for (int nt = 0; nt < 8; nt++) {
            mx0 = fmaxf(mx0, fmaxf(s[nt][0], s[nt][1]));
            mx1 = fmaxf(mx1, fmaxf(s[nt][2], s[nt][3]));
        }
        mx0 = fmaxf(mx0, __shfl_xor_sync(0xffffffffu, mx0, 1));
        mx0 = fmaxf(mx0, __shfl_xor_sync(0xffffffffu, mx0, 2));
        mx1 = fmaxf(mx1, __shfl_xor_sync(0xffffffffu, mx1, 1));
        mx1 = fmaxf(mx1, __shfl_xor_sync(0xffffffffu, mx1, 2));
        const float mn0 = fmaxf(m0, mx0), mn1 = fmaxf(m1, mx1);
        const float al0 = __expf(m0 - mn0), al1 = __expf(m1 - mn1);
        m0 = mn0; m1 = mn1;

        float ps0 = 0.f, ps1 = 0.f;
        #pragma unroll
        for (int nt = 0; nt < 8; nt++) {
            float p0 = __expf(s[nt][0] - mn0);
            float p1 = __expf(s[nt][1] - mn0);
            float p2 = __expf(s[nt][2] - mn1);
            float p3 = __expf(s[nt][3] - mn1);
            ps0 += p0 + p1; ps1 += p2 + p3;
            const int cl = nt * 8 + 2 * fc;
            Ps[(wq + fr) * 68 + cl]     = p0;
            Ps[(wq + fr) * 68 + cl + 1] = p1;
            Ps[(wq + fr + 8) * 68 + cl]     = p2;
            Ps[(wq + fr + 8) * 68 + cl + 1] = p3;
        }
        ps0 += __shfl_xor_sync(0xffffffffu, ps0, 1);
        ps0 += __shfl_xor_sync(0xffffffffu, ps0, 2);
        ps1 += __shfl_xor_sync(0xffffffffu, ps1, 1);
        ps1 += __shfl_xor_sync(0xffffffffu, ps1, 2);
        l0 = l0 * al0 + ps0;
        l1 = l1 * al1 + ps1;
        #pragma unroll
        for (int nt = 0; nt < 8; nt++) {
            o[nt][0] *= al0; o[nt][1] *= al0;
            o[nt][2] *= al1; o[nt][3] *= al1;
        }
        __syncwarp();

        // ---- O += P V ----
        #pragma unroll
        for (int ks = 0; ks < 8; ks++) {
            const int c = ks * 8 + fc;
            uint32_t a[4];
            a[0] = __float_as_uint(Ps[(wq + fr) * 68 + c]);
            a[1] = __float_as_uint(Ps[(wq + fr + 8) * 68 + c]);
            a[2] = __float_as_uint(Ps[(wq + fr) * 68 + c + 4]);
            a[3] = __float_as_uint(Ps[(wq + fr + 8) * 68 + c + 4]);
            #pragma unroll
            for (int nt = 0; nt < 8; nt++) {
                uint32_t b[2];
                b[0] = __float_as_uint(Vb[c * 72 + nt * 8 + fr]);
                b[1] = __float_as_uint(Vb[(c + 4) * 72 + nt * 8 + fr]);
                mma_tf32(o[nt], a, b);
            }
        }
        __syncthreads();
    }

    // ---- epilogue: O/l -> g_y [B,T,C], tf32-rounded (proj mainloop consumes raw) ----
    const float inv0 = 1.0f / l0, inv1 = 1.0f / l1;
    const int b = bh >> 4, h = bh & 15;
    const int t0 = q0 + wq + fr, t1 = t0 + 8;
    #pragma unroll
    for (int nt = 0; nt < 8; nt++) {
        const int d = nt * 8 + 2 * fc;
        *(float2*)(g_y + (size_t)(b * TDIM + t0) * CDIM + h * HD + d) =
            make_float2(__uint_as_float(cvt_tf32(o[nt][0] * inv0)),
                        __uint_as_float(cvt_tf32(o[nt][1] * inv0)));
        *(float2*)(g_y + (size_t)(b * TDIM + t1) * CDIM + h * HD + d) =
            make_float2(__uint_as_float(cvt_tf32(o[nt][2] * inv1)),
                        __uint_as_float(cvt_tf32(o[nt][3] * inv1)));
    }
}

// ================= launch =================
extern "C" void kernel_launch(void* const* d_in, const int* in_sizes, int n_in,
                              void* d_out, int out_size)
{
    const float* x     = (const float*)d_in[0];
    const float* sinp  = (const float*)d_in[1];
    const float* cosp  = (const float*)d_in[2];
    const float* Wqkv  = (const float*)d_in[3];
    const float* Wproj = (const float*)d_in[4];
    float* out = (float*)d_out;

    float* wt_qkv;  cudaGetSymbolAddress((void**)&wt_qkv,  g_wt_qkv);
    float* wt_proj; cudaGetSymbolAddress((void**)&wt_proj, g_wt_proj);

    cudaFuncSetAttribute(flash_mma,     cudaFuncAttributeMaxDynamicSharedMemorySize, FA_SMEM);
    cudaFuncSetAttribute(gemm_qkv_mma,  cudaFuncAttributeMaxDynamicSharedMemorySize, GSMEM);
    cudaFuncSetAttribute(gemm_proj_mma, cudaFuncAttributeMaxDynamicSharedMemorySize, GSMEM);

    cvt_x32_kernel<<<MDIM * CDIM / 4 / 256, 256>>>(x);
    transpose_cvt<<<dim3(NQKV / 32, CDIM / 32), 256>>>(Wqkv,  wt_qkv,  NQKV);
    transpose_cvt<<<dim3(CDIM / 32, CDIM / 32), 256>>>(Wproj, wt_proj, CDIM);

    gemm_qkv_mma<<<dim3(NQKV / 128, MDIM / 128), 256, GSMEM>>>(sinp, cosp);
    flash_mma<<<dim3(BDIM * NH, TDIM / 64), 128, FA_SMEM>>>();
    gemm_proj_mma<<<dim3(CDIM / 128, MDIM / 128), 256, GSMEM>>>(out);
}

// round 8
// speedup vs baseline: 3.5672x; 1.1101x over previous
#include <cuda_runtime.h>
#include <cstdint>
#include <math.h>

#define BDIM 2
#define TDIM 2048
#define CDIM 1024
#define NH 16
#define HD 64
#define MDIM (BDIM*TDIM)   // 4096
#define NQKV (3*CDIM)      // 3072

// Scratch (allocation-free rule: __device__ globals)
__device__ float g_q[BDIM*NH*TDIM*HD];
__device__ float g_k[BDIM*NH*TDIM*HD];
__device__ float g_v[BDIM*NH*TDIM*HD];
__device__ float g_y[MDIM*CDIM];          // tf32-rounded by flash epilogue
__device__ float g_x32[MDIM*CDIM];        // x, tf32-rounded
__device__ float g_wt_qkv[NQKV*CDIM];     // W_qkv^T [N][K], tf32-rounded
__device__ float g_wt_proj[CDIM*CDIM];    // W_proj^T [N][K], tf32-rounded

__device__ __forceinline__ uint32_t cvt_tf32(float x) {
    uint32_t r; asm("cvt.rna.tf32.f32 %0, %1;" : "=r"(r) : "f"(x)); return r;
}
__device__ __forceinline__ void mma_tf32(float* d, const uint32_t* a, const uint32_t* b) {
    asm volatile(
        "mma.sync.aligned.m16n8k8.row.col.f32.tf32.tf32.f32 "
        "{%0,%1,%2,%3}, {%4,%5,%6,%7}, {%8,%9}, {%0,%1,%2,%3};"
        : "+f"(d[0]), "+f"(d[1]), "+f"(d[2]), "+f"(d[3])
        : "r"(a[0]), "r"(a[1]), "r"(a[2]), "r"(a[3]), "r"(b[0]), "r"(b[1]));
}
__device__ __forceinline__ void cp16(uint32_t daddr, const void* g) {
    asm volatile("cp.async.cg.shared.global [%0], [%1], 16;" :: "r"(daddr), "l"(g) : "memory");
}
// ldmatrix x4: each 8x8-b16 matrix == 8 rows x 4 tf32; lane gets (row l>>2, col l&3)
__device__ __forceinline__ void ldsm4(uint32_t* r, uint32_t saddr) {
    asm volatile("ldmatrix.sync.aligned.m8n8.x4.shared.b16 {%0,%1,%2,%3}, [%4];"
        : "=r"(r[0]), "=r"(r[1]), "=r"(r[2]), "=r"(r[3]) : "r"(saddr));
}

// ================= pre-round x to tf32 =================
__global__ __launch_bounds__(256) void cvt_x32_kernel(const float* __restrict__ x)
{
    int i = blockIdx.x * 256 + threadIdx.x;
    float4 v = ((const float4*)x)[i];
    ((uint4*)g_x32)[i] = make_uint4(cvt_tf32(v.x), cvt_tf32(v.y), cvt_tf32(v.z), cvt_tf32(v.w));
}

// ================= transpose + tf32 convert =================
__global__ __launch_bounds__(256) void transpose_cvt(
    const float* __restrict__ W, float* __restrict__ WT, int N)
{
    __shared__ float t[32][33];
    int n0 = blockIdx.x * 32, k0 = blockIdx.y * 32;
    int tx = threadIdx.x & 31, ty = threadIdx.x >> 5;
    #pragma unroll
    for (int i = 0; i < 4; i++)
        t[ty + i * 8][tx] = W[(size_t)(k0 + ty + i * 8) * N + n0 + tx];
    __syncthreads();
    #pragma unroll
    for (int i = 0; i < 4; i++)
        WT[(size_t)(n0 + ty + i * 8) * CDIM + k0 + tx] =
            __uint_as_float(cvt_tf32(t[tx][ty + i * 8]));
}

// ================= tf32 mma.sync GEMM, 3-stage cp.async + ldmatrix =================
// BM=BN=128, BK=16, 8 warps (2x4), warp tile 64x32. smem [row][20] pad.
#define GPITCH (128*20)
#define GSMEM (6*GPITCH*4)     // 61440 B

__device__ __forceinline__ void gemm_issue(
    uint32_t* As, uint32_t* Bs, const float* Ap, const float* Bp,
    int stage, int k0, int lr, int lc4)
{
    #pragma unroll
    for (int i = 0; i < 2; i++) {
        const int r = lr + i * 64;
        cp16((uint32_t)__cvta_generic_to_shared(As + stage * GPITCH + r * 20 + lc4),
             Ap + (size_t)r * CDIM + k0 + lc4);
        cp16((uint32_t)__cvta_generic_to_shared(Bs + stage * GPITCH + r * 20 + lc4),
             Bp + (size_t)r * CDIM + k0 + lc4);
    }
    asm volatile("cp.async.commit_group;" ::: "memory");
}

__device__ __forceinline__ void mma_mainloop(
    const float* __restrict__ Ap, const float* __restrict__ Bp,
    float (&acc)[4][4][4], int tid, uint32_t* smem)
{
    uint32_t* As = smem;               // [3][128][20]
    uint32_t* Bs = smem + 3 * GPITCH;
    const uint32_t As_s = (uint32_t)__cvta_generic_to_shared(As);
    const uint32_t Bs_s = (uint32_t)__cvta_generic_to_shared(Bs);
    const int lane = tid & 31, wid = tid >> 5;
    const int wm = wid >> 2, wn = wid & 3;
    const int lr = tid >> 2, lc4 = (tid & 3) * 4;
    const int lq = lane & 7, j = lane >> 3;   // ldmatrix: row-in-matrix, matrix id

    // lane address offsets (bytes) for ldmatrix x4
    uint32_t a_off[4], b_off[2];
    #pragma unroll
    for (int mt = 0; mt < 4; mt++)
        a_off[mt] = ((wm * 64 + mt * 16 + (j & 1) * 8 + lq) * 20 + (j >> 1) * 4) * 4;
    #pragma unroll
    for (int p = 0; p < 2; p++)
        b_off[p] = ((wn * 32 + (2 * p + (j >> 1)) * 8 + lq) * 20 + (j & 1) * 4) * 4;

    #pragma unroll
    for (int mt = 0; mt < 4; mt++)
        #pragma unroll
        for (int nt = 0; nt < 4; nt++)
            #pragma unroll
            for (int jj = 0; jj < 4; jj++) acc[mt][nt][jj] = 0.f;

    gemm_issue(As, Bs, Ap, Bp, 0, 0, lr, lc4);
    gemm_issue(As, Bs, Ap, Bp, 1, 16, lr, lc4);

    int cur = 0, nxt = 2;
    for (int it = 0; it < 64; it++) {
        if (it < 63) asm volatile("cp.async.wait_group 1;" ::: "memory");
        else         asm volatile("cp.async.wait_group 0;" ::: "memory");
        __syncthreads();
        if (it + 2 < 64) {
            gemm_issue(As, Bs, Ap, Bp, nxt, (it + 2) * 16, lr, lc4);
            if (++nxt == 3) nxt = 0;
        }

        const uint32_t Ab = As_s + cur * (GPITCH * 4);
        const uint32_t Bb = Bs_s + cur * (GPITCH * 4);
        #pragma unroll
        for (int ks = 0; ks < 2; ks++) {
            uint32_t af[4][4];
            #pragma unroll
            for (int mt = 0; mt < 4; mt++) ldsm4(af[mt], Ab + a_off[mt] + ks * 32);
            uint32_t bf[8];
            #pragma unroll
            for (int p = 0; p < 2; p++) ldsm4(bf + 4 * p, Bb + b_off[p] + ks * 32);
            #pragma unroll
            for (int mt = 0; mt < 4; mt++)
                #pragma unroll
                for (int nt = 0; nt < 4; nt++)
                    mma_tf32(acc[mt][nt], af[mt], &bf[2 * nt]);
        }
        if (++cur == 3) cur = 0;
    }
}

__global__ __launch_bounds__(256) void gemm_qkv_mma(
    const float* __restrict__ sinp, const float* __restrict__ cosp)
{
    extern __shared__ uint32_t smu[];
    const int tid = threadIdx.x;
    const int m0 = blockIdx.y * 128, n0 = blockIdx.x * 128;
    float acc[4][4][4];
    mma_mainloop(g_x32 + (size_t)m0 * CDIM, g_wt_qkv + (size_t)n0 * CDIM, acc, tid, smu);

    const int lane = tid & 31, wid = tid >> 5;
    const int wm = wid >> 2, wn = wid & 3;
    const int sec = n0 >> 10;
    const int nb = n0 & 1023;
    float* dst = (sec == 0) ? g_q : (sec == 1 ? g_k : g_v);

    #pragma unroll
    for (int mt = 0; mt < 4; mt++) {
        #pragma unroll
        for (int nt = 0; nt < 4; nt++) {
            const int col = wn * 32 + nt * 8 + (lane & 3) * 2;
            const int nc = nb + col;
            const int h = nc >> 6, d = nc & 63;
            #pragma unroll
            for (int half = 0; half < 2; half++) {
                const int row = m0 + wm * 64 + mt * 16 + (lane >> 2) + half * 8;
                const int b = row >> 11, t = row & 2047;
                float v0 = acc[mt][nt][half * 2], v1 = acc[mt][nt][half * 2 + 1];
                float o0, o1;
                if (sec < 2) {
                    float ca = cosp[t * HD + d], sa = sinp[t * HD + d];
                    o0 = v0 * ca - v1 * sa;
                    o1 = v1 * ca + v0 * sa;
                } else { o0 = v0; o1 = v1; }
                *(float2*)(dst + ((((size_t)b * NH + h) * TDIM + t) * HD + d)) =
                    make_float2(__uint_as_float(cvt_tf32(o0)), __uint_as_float(cvt_tf32(o1)));
            }
        }
    }
}

__global__ __launch_bounds__(256) void gemm_proj_mma(float* __restrict__ out)
{
    extern __shared__ uint32_t smu[];
    const int tid = threadIdx.x;
    const int m0 = blockIdx.y * 128, n0 = blockIdx.x * 128;
    float acc[4][4][4];
    mma_mainloop(g_y + (size_t)m0 * CDIM, g_wt_proj + (size_t)n0 * CDIM, acc, tid, smu);

    const int lane = tid & 31, wid = tid >> 5;
    const int wm = wid >> 2, wn = wid & 3;
    #pragma unroll
    for (int mt = 0; mt < 4; mt++) {
        #pragma unroll
        for (int nt = 0; nt < 4; nt++) {
            const int col = n0 + wn * 32 + nt * 8 + (lane & 3) * 2;
            #pragma unroll
            for (int half = 0; half < 2; half++) {
                const int row = m0 + wm * 64 + mt * 16 + (lane >> 2) + half * 8;
                *(float2*)(out + (size_t)row * CDIM + col) =
                    make_float2(acc[mt][nt][half * 2], acc[mt][nt][half * 2 + 1]);
            }
        }
    }
}

// ================= flash attention on mma.sync tf32 + ldmatrix =================
// CTA: 64 q-rows, 4 warps (warp = 16 q x 64 k). BK=64, cp.async double buffer.
#define FA_SMEM 106496

__global__ __launch_bounds__(128) void flash_mma()
{
    extern __shared__ float sm[];
    float* Qs = sm;                 // [64][68]
    float* Ps = sm + 4352;          // [64][68]
    float* KsB = sm + 8704;         // [2][64][68]
    float* VsB = sm + 17408;        // [2][64][72]

    const int bh = blockIdx.x;
    const int qt = 31 - blockIdx.y;         // long CTAs first
    const int q0 = qt * 64;
    const int tid = threadIdx.x;
    const int lane = tid & 31, wid = tid >> 5;
    const int fr = lane >> 2, fc = lane & 3;
    const int lq = lane & 7, j = lane >> 3;
    const int wq = wid * 16;

    const float* qb = g_q + (size_t)bh * TDIM * HD;
    const float* kb = g_k + (size_t)bh * TDIM * HD;
    const float* vb = g_v + (size_t)bh * TDIM * HD;

    const uint32_t Qs_s = (uint32_t)__cvta_generic_to_shared(Qs);
    const uint32_t Ps_s = (uint32_t)__cvta_generic_to_shared(Ps);
    const uint32_t Ks_s = (uint32_t)__cvta_generic_to_shared(KsB);

    // ldmatrix lane offsets (bytes)
    const uint32_t q_off = ((wq + (j & 1) * 8 + lq) * 68 + (j >> 1) * 4) * 4;  // Q and P (A-side)
    uint32_t k_off[4];
    #pragma unroll
    for (int p = 0; p < 4; p++)
        k_off[p] = (((2 * p + (j >> 1)) * 8 + lq) * 68 + (j & 1) * 4) * 4;

    #pragma unroll
    for (int i = 0; i < 8; i++) {
        int lin = tid + i * 128;
        int r = lin >> 4, c4 = (lin & 15) * 4;
        *(float4*)(Qs + r * 68 + c4) = *(const float4*)(qb + (size_t)(q0 + r) * HD + c4);
    }
    #pragma unroll
    for (int i = 0; i < 8; i++) {
        int lin = tid + i * 128;
        int r = lin >> 4, c4 = (lin & 15) * 4;
        cp16((uint32_t)__cvta_generic_to_shared(KsB + r * 68 + c4),
             kb + (size_t)r * HD + c4);
        cp16((uint32_t)__cvta_generic_to_shared(VsB + r * 72 + c4),
             vb + (size_t)r * HD + c4);
    }
    asm volatile("cp.async.commit_group;" ::: "memory");

    float o[8][4];
    #pragma unroll
    for (int nt = 0; nt < 8; nt++)
        #pragma unroll
        for (int jj = 0; jj < 4; jj++) o[nt][jj] = 0.f;
    float m0 = -1e30f, m1 = -1e30f, l0 = 0.f, l1 = 0.f;

    for (int kt = 0; kt <= qt; kt++) {
        const int buf = kt & 1;
        if (kt < qt) {
            const int kr = (kt + 1) * 64;
            float* Kn = KsB + (buf ^ 1) * 4352;
            float* Vn = VsB + (buf ^ 1) * 4608;
            #pragma unroll
            for (int i = 0; i < 8; i++) {
                int lin = tid + i * 128;
                int r = lin >> 4, c4 = (lin & 15) * 4;
                cp16((uint32_t)__cvta_generic_to_shared(Kn + r * 68 + c4),
                     kb + (size_t)(kr + r) * HD + c4);
                cp16((uint32_t)__cvta_generic_to_shared(Vn + r * 72 + c4),
                     vb + (size_t)(kr + r) * HD + c4);
            }
            asm volatile("cp.async.commit_group;" ::: "memory");
            asm volatile("cp.async.wait_group 1;" ::: "memory");
        } else {
            asm volatile("cp.async.wait_group 0;" ::: "memory");
        }
        __syncthreads();

        const uint32_t Kb_s = Ks_s + buf * (4352 * 4);
        const float* Vb = VsB + buf * 4608;

        // ---- S = Q K^T ----
        float s[8][4];
        #pragma unroll
        for (int nt = 0; nt < 8; nt++)
            #pragma unroll
            for (int jj = 0; jj < 4; jj++) s[nt][jj] = 0.f;
        #pragma unroll
        for (int ks = 0; ks < 8; ks++) {
            uint32_t a[4];
            ldsm4(a, Qs_s + q_off + ks * 32);
            uint32_t kf[16];
            #pragma unroll
            for (int p = 0; p < 4; p++) ldsm4(kf + 4 * p, Kb_s + k_off[p] + ks * 32);
            #pragma unroll
            for (int nt = 0; nt < 8; nt++)
                mma_tf32(s[nt], a, &kf[2 * nt]);
        }
        #pragma unroll
        for (int nt = 0; nt < 8; nt++)
            #pragma unroll
            for (int jj = 0; jj < 4; jj++) s[nt][jj] *= 0.125f;

        if (kt == qt) {
            const int r0 = wq + fr, r1 = r0 + 8;
            #pragma unroll
            for (int nt = 0; nt < 8; nt++) {
                const int cl = nt * 8 + 2 * fc;
                if (cl > r0)     s[nt][0] = -1e30f;
                if (cl + 1 > r0) s[nt][1] = -1e30f;
                if (cl > r1)     s[nt][2] = -1e30f;
                if (cl + 1 > r1) s[nt][3] = -1e30f;
            }
        }

        // ---- online softmax (warp-local quad shuffles) ----
        float mx0 = -1e30f, mx1 = -1e30f;
        #pragma unroll
        for (int nt = 0; nt < 8; nt++) {
            mx0 = fmaxf(mx0, fmaxf(s[nt][0], s[nt][1]));
            mx1 = fmaxf(mx1, fmaxf(s[nt][2], s[nt][3]));
        }
        mx0 = fmaxf(mx0, __shfl_xor_sync(0xffffffffu, mx0, 1));
        mx0 = fmaxf(mx0, __shfl_xor_sync(0xffffffffu, mx0, 2));
        mx1 = fmaxf(mx1, __shfl_xor_sync(0xffffffffu, mx1, 1));
        mx1 = fmaxf(mx1, __shfl_xor_sync(0xffffffffu, mx1, 2));
        const float mn0 = fmaxf(m0, mx0), mn1 = fmaxf(m1, mx1);
        const float al0 = __expf(m0 - mn0), al1 = __expf(m1 - mn1);
        m0 = mn0; m1 = mn1;

        float ps0 = 0.f, ps1 = 0.f;
        #pragma unroll
        for (int nt = 0; nt < 8; nt++) {
            float p0 = __expf(s[nt][0] - mn0);
            float p1 = __expf(s[nt][1] - mn0);
            float p2 = __expf(s[nt][2] - mn1);
            float p3 = __expf(s[nt][3] - mn1);
            ps0 += p0 + p1; ps1 += p2 + p3;
            const int cl = nt * 8 + 2 * fc;
            Ps[(wq + fr) * 68 + cl]     = p0;
            Ps[(wq + fr) * 68 + cl + 1] = p1;
            Ps[(wq + fr + 8) * 68 + cl]     = p2;
            Ps[(wq + fr + 8) * 68 + cl + 1] = p3;
        }
        ps0 += __shfl_xor_sync(0xffffffffu, ps0, 1);
        ps0 += __shfl_xor_sync(0xffffffffu, ps0, 2);
        ps1 += __shfl_xor_sync(0xffffffffu, ps1, 1);
        ps1 += __shfl_xor_sync(0xffffffffu, ps1, 2);
        l0 = l0 * al0 + ps0;
        l1 = l1 * al1 + ps1;
        #pragma unroll
        for (int nt = 0; nt < 8; nt++) {
            o[nt][0] *= al0; o[nt][1] *= al0;
            o[nt][2] *= al1; o[nt][3] *= al1;
        }
        __syncwarp();

        // ---- O += P V ----
        #pragma unroll
        for (int ks = 0; ks < 8; ks++) {
            const int c = ks * 8 + fc;
            uint32_t a[4];
            ldsm4(a, Ps_s + q_off + ks * 32);
            #pragma unroll
            for (int nt = 0; nt < 8; nt++) {
                uint32_t b[2];
                b[0] = __float_as_uint(Vb[c * 72 + nt * 8 + fr]);
                b[1] = __float_as_uint(Vb[(c + 4) * 72 + nt * 8 + fr]);
                mma_tf32(o[nt], a, b);
            }
        }
        __syncthreads();
    }

    // ---- epilogue: O/l -> g_y [B,T,C], tf32-rounded ----
    const float inv0 = 1.0f / l0, inv1 = 1.0f / l1;
    const int b = bh >> 4, h = bh & 15;
    const int t0 = q0 + wq + fr, t1 = t0 + 8;
    #pragma unroll
    for (int nt = 0; nt < 8; nt++) {
        const int d = nt * 8 + 2 * fc;
        *(float2*)(g_y + (size_t)(b * TDIM + t0) * CDIM + h * HD + d) =
            make_float2(__uint_as_float(cvt_tf32(o[nt][0] * inv0)),
                        __uint_as_float(cvt_tf32(o[nt][1] * inv0)));
        *(float2*)(g_y + (size_t)(b * TDIM + t1) * CDIM + h * HD + d) =
            make_float2(__uint_as_float(cvt_tf32(o[nt][2] * inv1)),
                        __uint_as_float(cvt_tf32(o[nt][3] * inv1)));
    }
}

// ================= launch =================
extern "C" void kernel_launch(void* const* d_in, const int* in_sizes, int n_in,
                              void* d_out, int out_size)
{
    const float* x     = (const float*)d_in[0];
    const float* sinp  = (const float*)d_in[1];
    const float* cosp  = (const float*)d_in[2];
    const float* Wqkv  = (const float*)d_in[3];
    const float* Wproj = (const float*)d_in[4];
    float* out = (float*)d_out;

    float* wt_qkv;  cudaGetSymbolAddress((void**)&wt_qkv,  g_wt_qkv);
    float* wt_proj; cudaGetSymbolAddress((void**)&wt_proj, g_wt_proj);

    cudaFuncSetAttribute(flash_mma,     cudaFuncAttributeMaxDynamicSharedMemorySize, FA_SMEM);
    cudaFuncSetAttribute(gemm_qkv_mma,  cudaFuncAttributeMaxDynamicSharedMemorySize, GSMEM);
    cudaFuncSetAttribute(gemm_proj_mma, cudaFuncAttributeMaxDynamicSharedMemorySize, GSMEM);

    cvt_x32_kernel<<<MDIM * CDIM / 4 / 256, 256>>>(x);
    transpose_cvt<<<dim3(NQKV / 32, CDIM / 32), 256>>>(Wqkv,  wt_qkv,  NQKV);
    transpose_cvt<<<dim3(CDIM / 32, CDIM / 32), 256>>>(Wproj, wt_proj, CDIM);

    gemm_qkv_mma<<<dim3(NQKV / 128, MDIM / 128), 256, GSMEM>>>(sinp, cosp);
    flash_mma<<<dim3(BDIM * NH, TDIM / 64), 128, FA_SMEM>>>();
    gemm_proj_mma<<<dim3(CDIM / 128, MDIM / 128), 256, GSMEM>>>(out);
}

// round 9
// speedup vs baseline: 3.8304x; 1.0738x over previous
#include <cuda_runtime.h>
#include <cstdint>
#include <math.h>

#define BDIM 2
#define TDIM 2048
#define CDIM 1024
#define NH 16
#define HD 64
#define MDIM (BDIM*TDIM)   // 4096
#define NQKV (3*CDIM)      // 3072

// Scratch (allocation-free rule: __device__ globals)
__device__ float g_q[BDIM*NH*TDIM*HD];
__device__ float g_k[BDIM*NH*TDIM*HD];
__device__ float g_vt[BDIM*NH*HD*TDIM];   // V transposed: [bh][d][t]
__device__ float g_y[MDIM*CDIM];          // tf32-rounded by flash epilogue
__device__ float g_x32[MDIM*CDIM];        // x, tf32-rounded
__device__ float g_wt_qkv[NQKV*CDIM];     // W_qkv^T [N][K], tf32-rounded
__device__ float g_wt_proj[CDIM*CDIM];    // W_proj^T [N][K], tf32-rounded

__device__ __forceinline__ uint32_t cvt_tf32(float x) {
    uint32_t r; asm("cvt.rna.tf32.f32 %0, %1;" : "=r"(r) : "f"(x)); return r;
}
__device__ __forceinline__ void mma_tf32(float* d, const uint32_t* a, const uint32_t* b) {
    asm volatile(
        "mma.sync.aligned.m16n8k8.row.col.f32.tf32.tf32.f32 "
        "{%0,%1,%2,%3}, {%4,%5,%6,%7}, {%8,%9}, {%0,%1,%2,%3};"
        : "+f"(d[0]), "+f"(d[1]), "+f"(d[2]), "+f"(d[3])
        : "r"(a[0]), "r"(a[1]), "r"(a[2]), "r"(a[3]), "r"(b[0]), "r"(b[1]));
}
__device__ __forceinline__ void cp16(uint32_t daddr, const void* g) {
    asm volatile("cp.async.cg.shared.global [%0], [%1], 16;" :: "r"(daddr), "l"(g) : "memory");
}
__device__ __forceinline__ void ldsm4(uint32_t* r, uint32_t saddr) {
    asm volatile("ldmatrix.sync.aligned.m8n8.x4.shared.b16 {%0,%1,%2,%3}, [%4];"
        : "=r"(r[0]), "=r"(r[1]), "=r"(r[2]), "=r"(r[3]) : "r"(saddr));
}

// ================= pre-round x to tf32 =================
__global__ __launch_bounds__(256) void cvt_x32_kernel(const float* __restrict__ x)
{
    int i = blockIdx.x * 256 + threadIdx.x;
    float4 v = ((const float4*)x)[i];
    ((uint4*)g_x32)[i] = make_uint4(cvt_tf32(v.x), cvt_tf32(v.y), cvt_tf32(v.z), cvt_tf32(v.w));
}

// ================= transpose + tf32 convert =================
__global__ __launch_bounds__(256) void transpose_cvt(
    const float* __restrict__ W, float* __restrict__ WT, int N)
{
    __shared__ float t[32][33];
    int n0 = blockIdx.x * 32, k0 = blockIdx.y * 32;
    int tx = threadIdx.x & 31, ty = threadIdx.x >> 5;
    #pragma unroll
    for (int i = 0; i < 4; i++)
        t[ty + i * 8][tx] = W[(size_t)(k0 + ty + i * 8) * N + n0 + tx];
    __syncthreads();
    #pragma unroll
    for (int i = 0; i < 4; i++)
        WT[(size_t)(n0 + ty + i * 8) * CDIM + k0 + tx] =
            __uint_as_float(cvt_tf32(t[tx][ty + i * 8]));
}

// ================= tf32 mma.sync GEMM, 4-stage cp.async + ldmatrix =================
// BM=BN=128, BK=16, 8 warps (2x4), warp tile 64x32. smem [row][20] pad.
#define GPITCH (128*20)
#define GSMEM (8*GPITCH*4)     // 4 stages x (A+B) = 81920 B

__device__ __forceinline__ void gemm_issue(
    uint32_t* As, uint32_t* Bs, const float* Ap, const float* Bp,
    int stage, int k0, int lr, int lc4)
{
    #pragma unroll
    for (int i = 0; i < 2; i++) {
        const int r = lr + i * 64;
        cp16((uint32_t)__cvta_generic_to_shared(As + stage * GPITCH + r * 20 + lc4),
             Ap + (size_t)r * CDIM + k0 + lc4);
        cp16((uint32_t)__cvta_generic_to_shared(Bs + stage * GPITCH + r * 20 + lc4),
             Bp + (size_t)r * CDIM + k0 + lc4);
    }
    asm volatile("cp.async.commit_group;" ::: "memory");
}

__device__ __forceinline__ void mma_mainloop(
    const float* __restrict__ Ap, const float* __restrict__ Bp,
    float (&acc)[4][4][4], int tid, uint32_t* smem)
{
    uint32_t* As = smem;               // [4][128][20]
    uint32_t* Bs = smem + 4 * GPITCH;
    const uint32_t As_s = (uint32_t)__cvta_generic_to_shared(As);
    const uint32_t Bs_s = (uint32_t)__cvta_generic_to_shared(Bs);
    const int lane = tid & 31, wid = tid >> 5;
    const int wm = wid >> 2, wn = wid & 3;
    const int lr = tid >> 2, lc4 = (tid & 3) * 4;
    const int lq = lane & 7, j = lane >> 3;

    uint32_t a_off[4], b_off[2];
    #pragma unroll
    for (int mt = 0; mt < 4; mt++)
        a_off[mt] = ((wm * 64 + mt * 16 + (j & 1) * 8 + lq) * 20 + (j >> 1) * 4) * 4;
    #pragma unroll
    for (int p = 0; p < 2; p++)
        b_off[p] = ((wn * 32 + (2 * p + (j >> 1)) * 8 + lq) * 20 + (j & 1) * 4) * 4;

    #pragma unroll
    for (int mt = 0; mt < 4; mt++)
        #pragma unroll
        for (int nt = 0; nt < 4; nt++)
            #pragma unroll
            for (int jj = 0; jj < 4; jj++) acc[mt][nt][jj] = 0.f;

    gemm_issue(As, Bs, Ap, Bp, 0, 0, lr, lc4);
    gemm_issue(As, Bs, Ap, Bp, 1, 16, lr, lc4);
    gemm_issue(As, Bs, Ap, Bp, 2, 32, lr, lc4);

    for (int it = 0; it < 64; it++) {
        if (it < 62)      asm volatile("cp.async.wait_group 2;" ::: "memory");
        else if (it < 63) asm volatile("cp.async.wait_group 1;" ::: "memory");
        else              asm volatile("cp.async.wait_group 0;" ::: "memory");
        __syncthreads();
        if (it + 3 < 64)
            gemm_issue(As, Bs, Ap, Bp, (it + 3) & 3, (it + 3) * 16, lr, lc4);

        const int cur = it & 3;
        const uint32_t Ab = As_s + cur * (GPITCH * 4);
        const uint32_t Bb = Bs_s + cur * (GPITCH * 4);
        #pragma unroll
        for (int ks = 0; ks < 2; ks++) {
            uint32_t af[4][4];
            #pragma unroll
            for (int mt = 0; mt < 4; mt++) ldsm4(af[mt], Ab + a_off[mt] + ks * 32);
            uint32_t bf[8];
            #pragma unroll
            for (int p = 0; p < 2; p++) ldsm4(bf + 4 * p, Bb + b_off[p] + ks * 32);
            #pragma unroll
            for (int mt = 0; mt < 4; mt++)
                #pragma unroll
                for (int nt = 0; nt < 4; nt++)
                    mma_tf32(acc[mt][nt], af[mt], &bf[2 * nt]);
        }
    }
}

__global__ __launch_bounds__(256) void gemm_qkv_mma(
    const float* __restrict__ sinp, const float* __restrict__ cosp)
{
    extern __shared__ uint32_t smu[];
    const int tid = threadIdx.x;
    const int m0 = blockIdx.y * 128, n0 = blockIdx.x * 128;
    float acc[4][4][4];
    mma_mainloop(g_x32 + (size_t)m0 * CDIM, g_wt_qkv + (size_t)n0 * CDIM, acc, tid, smu);

    const int lane = tid & 31, wid = tid >> 5;
    const int wm = wid >> 2, wn = wid & 3;
    const int sec = n0 >> 10;
    const int nb = n0 & 1023;

    #pragma unroll
    for (int mt = 0; mt < 4; mt++) {
        #pragma unroll
        for (int nt = 0; nt < 4; nt++) {
            const int col = wn * 32 + nt * 8 + (lane & 3) * 2;
            const int nc = nb + col;
            const int h = nc >> 6, d = nc & 63;
            #pragma unroll
            for (int half = 0; half < 2; half++) {
                const int row = m0 + wm * 64 + mt * 16 + (lane >> 2) + half * 8;
                const int b = row >> 11, t = row & 2047;
                const int bh = b * NH + h;
                float v0 = acc[mt][nt][half * 2], v1 = acc[mt][nt][half * 2 + 1];
                if (sec < 2) {
                    float ca = cosp[t * HD + d], sa = sinp[t * HD + d];
                    float o0 = v0 * ca - v1 * sa;
                    float o1 = v1 * ca + v0 * sa;
                    float* dst = (sec == 0) ? g_q : g_k;
                    *(float2*)(dst + (((size_t)bh * TDIM + t) * HD + d)) =
                        make_float2(__uint_as_float(cvt_tf32(o0)), __uint_as_float(cvt_tf32(o1)));
                } else {
                    // V: store transposed [bh][d][t]
                    g_vt[((size_t)bh * HD + d) * TDIM + t]     = __uint_as_float(cvt_tf32(v0));
                    g_vt[((size_t)bh * HD + d + 1) * TDIM + t] = __uint_as_float(cvt_tf32(v1));
                }
            }
        }
    }
}

__global__ __launch_bounds__(256) void gemm_proj_mma(float* __restrict__ out)
{
    extern __shared__ uint32_t smu[];
    const int tid = threadIdx.x;
    const int m0 = blockIdx.y * 128, n0 = blockIdx.x * 128;
    float acc[4][4][4];
    mma_mainloop(g_y + (size_t)m0 * CDIM, g_wt_proj + (size_t)n0 * CDIM, acc, tid, smu);

    const int lane = tid & 31, wid = tid >> 5;
    const int wm = wid >> 2, wn = wid & 3;
    #pragma unroll
    for (int mt = 0; mt < 4; mt++) {
        #pragma unroll
        for (int nt = 0; nt < 4; nt++) {
            const int col = n0 + wn * 32 + nt * 8 + (lane & 3) * 2;
            #pragma unroll
            for (int half = 0; half < 2; half++) {
                const int row = m0 + wm * 64 + mt * 16 + (lane >> 2) + half * 8;
                *(float2*)(out + (size_t)row * CDIM + col) =
                    make_float2(acc[mt][nt][half * 2], acc[mt][nt][half * 2 + 1]);
            }
        }
    }
}

// ================= flash attention: mma.sync tf32, full-ldmatrix =================
// CTA: 64 q-rows, 4 warps (warp = 16 q x 64 k). BK=64, cp.async double buffer.
// smem floats: Qs[64][68] @0, Ps[64][68] @4352, Ks[2][64][68] @8704, Vt[2][64][68] @17408
#define FA_SMEM 104448

__global__ __launch_bounds__(128) void flash_mma()
{
    extern __shared__ float sm[];
    float* Qs = sm;                 // [64][68]
    float* Ps = sm + 4352;          // [64][68]
    float* KsB = sm + 8704;         // [2][64][68]
    float* VsB = sm + 17408;        // [2][64][68]  (Vt: rows=d, cols=t)

    const int bh = blockIdx.x;
    const int qt = 31 - blockIdx.y;         // long CTAs first
    const int q0 = qt * 64;
    const int tid = threadIdx.x;
    const int lane = tid & 31, wid = tid >> 5;
    const int fr = lane >> 2, fc = lane & 3;
    const int lq = lane & 7, j = lane >> 3;
    const int wq = wid * 16;

    const float* qb = g_q + (size_t)bh * TDIM * HD;
    const float* kb = g_k + (size_t)bh * TDIM * HD;
    const float* vtb = g_vt + (size_t)bh * HD * TDIM;

    const uint32_t Qs_s = (uint32_t)__cvta_generic_to_shared(Qs);
    const uint32_t Ps_s = (uint32_t)__cvta_generic_to_shared(Ps);
    const uint32_t Ks_s = (uint32_t)__cvta_generic_to_shared(KsB);
    const uint32_t Vs_s = (uint32_t)__cvta_generic_to_shared(VsB);

    const uint32_t q_off = ((wq + (j & 1) * 8 + lq) * 68 + (j >> 1) * 4) * 4;  // A-side (Q and P)
    uint32_t b_off[4];   // B-side lane offsets (K rows=t; Vt rows=d) — same pattern
    #pragma unroll
    for (int p = 0; p < 4; p++)
        b_off[p] = (((2 * p + (j >> 1)) * 8 + lq) * 68 + (j & 1) * 4) * 4;

    #pragma unroll
    for (int i = 0; i < 8; i++) {
        int lin = tid + i * 128;
        int r = lin >> 4, c4 = (lin & 15) * 4;
        *(float4*)(Qs + r * 68 + c4) = *(const float4*)(qb + (size_t)(q0 + r) * HD + c4);
    }
    #pragma unroll
    for (int i = 0; i < 8; i++) {
        int lin = tid + i * 128;
        int r = lin >> 4, c4 = (lin & 15) * 4;
        cp16((uint32_t)__cvta_generic_to_shared(KsB + r * 68 + c4),
             kb + (size_t)r * HD + c4);
        cp16((uint32_t)__cvta_generic_to_shared(VsB + r * 68 + c4),
             vtb + (size_t)r * TDIM + c4);          // row r = d, cols = t within tile 0
    }
    asm volatile("cp.async.commit_group;" ::: "memory");

    float o[8][4];
    #pragma unroll
    for (int nt = 0; nt < 8; nt++)
        #pragma unroll
        for (int jj = 0; jj < 4; jj++) o[nt][jj] = 0.f;
    float m0 = -1e30f, m1 = -1e30f, l0 = 0.f, l1 = 0.f;

    for (int kt = 0; kt <= qt; kt++) {
        const int buf = kt & 1;
        if (kt < qt) {
            const int kr = (kt + 1) * 64;
            float* Kn = KsB + (buf ^ 1) * 4352;
            float* Vn = VsB + (buf ^ 1) * 4352;
            #pragma unroll
            for (int i = 0; i < 8; i++) {
                int lin = tid + i * 128;
                int r = lin >> 4, c4 = (lin & 15) * 4;
                cp16((uint32_t)__cvta_generic_to_shared(Kn + r * 68 + c4),
                     kb + (size_t)(kr + r) * HD + c4);
                cp16((uint32_t)__cvta_generic_to_shared(Vn + r * 68 + c4),
                     vtb + (size_t)r * TDIM + kr + c4);
            }
            asm volatile("cp.async.commit_group;" ::: "memory");
            asm volatile("cp.async.wait_group 1;" ::: "memory");
        } else {
            asm volatile("cp.async.wait_group 0;" ::: "memory");
        }
        __syncthreads();

        const uint32_t Kb_s = Ks_s + buf * (4352 * 4);
        const uint32_t Vb_s = Vs_s + buf * (4352 * 4);

        // ---- S = Q K^T ----
        float s[8][4];
        #pragma unroll
        for (int nt = 0; nt < 8; nt++)
            #pragma unroll
            for (int jj = 0; jj < 4; jj++) s[nt][jj] = 0.f;
        #pragma unroll
        for (int ks = 0; ks < 8; ks++) {
            uint32_t a[4];
            ldsm4(a, Qs_s + q_off + ks * 32);
            uint32_t kf[16];
            #pragma unroll
            for (int p = 0; p < 4; p++) ldsm4(kf + 4 * p, Kb_s + b_off[p] + ks * 32);
            #pragma unroll
            for (int nt = 0; nt < 8; nt++)
                mma_tf32(s[nt], a, &kf[2 * nt]);
        }
        #pragma unroll
        for (int nt = 0; nt < 8; nt++)
            #pragma unroll
            for (int jj = 0; jj < 4; jj++) s[nt][jj] *= 0.125f;

        if (kt == qt) {
            const int r0 = wq + fr, r1 = r0 + 8;
            #pragma unroll
            for (int nt = 0; nt < 8; nt++) {
                const int cl = nt * 8 + 2 * fc;
                if (cl > r0)     s[nt][0] = -1e30f;
                if (cl + 1 > r0) s[nt][1] = -1e30f;
                if (cl > r1)     s[nt][2] = -1e30f;
                if (cl + 1 > r1) s[nt][3] = -1e30f;
            }
        }

        // ---- online softmax (warp-local quad shuffles) ----
        float mx0 = -1e30f, mx1 = -1e30f;
        #pragma unroll
        for (int nt = 0; nt < 8; nt++) {
            mx0 = fmaxf(mx0, fmaxf(s[nt][0], s[nt][1]));
            mx1 = fmaxf(mx1, fmaxf(s[nt][2], s[nt][3]));
        }
        mx0 = fmaxf(mx0, __shfl_xor_sync(0xffffffffu, mx0, 1));
        mx0 = fmaxf(mx0, __shfl_xor_sync(0xffffffffu, mx0, 2));
        mx1 = fmaxf(mx1, __shfl_xor_sync(0xffffffffu, mx1, 1));
        mx1 = fmaxf(mx1, __shfl_xor_sync(0xffffffffu, mx1, 2));
        const float mn0 = fmaxf(m0, mx0), mn1 = fmaxf(m1, mx1);
        const float al0 = __expf(m0 - mn0), al1 = __expf(m1 - mn1);
        m0 = mn0; m1 = mn1;

        float ps0 = 0.f, ps1 = 0.f;
        #pragma unroll
        for (int nt = 0; nt < 8; nt++) {
            float p0 = __expf(s[nt][0] - mn0);
            float p1 = __expf(s[nt][1] - mn0);
            float p2 = __expf(s[nt][2] - mn1);
            float p3 = __expf(s[nt][3] - mn1);
            ps0 += p0 + p1; ps1 += p2 + p3;
            const int cl = nt * 8 + 2 * fc;
            Ps[(wq + fr) * 68 + cl]     = p0;
            Ps[(wq + fr) * 68 + cl + 1] = p1;
            Ps[(wq + fr + 8) * 68 + cl]     = p2;
            Ps[(wq + fr + 8) * 68 + cl + 1] = p3;
        }
        ps0 += __shfl_xor_sync(0xffffffffu, ps0, 1);
        ps0 += __shfl_xor_sync(0xffffffffu, ps0, 2);
        ps1 += __shfl_xor_sync(0xffffffffu, ps1, 1);
        ps1 += __shfl_xor_sync(0xffffffffu, ps1, 2);
        l0 = l0 * al0 + ps0;
        l1 = l1 * al1 + ps1;
        #pragma unroll
        for (int nt = 0; nt < 8; nt++) {
            o[nt][0] *= al0; o[nt][1] *= al0;
            o[nt][2] *= al1; o[nt][3] *= al1;
        }
        __syncwarp();

        // ---- O += P V  (B-fragments via ldmatrix on Vt, same pattern as K) ----
        #pragma unroll
        for (int ks = 0; ks < 8; ks++) {
            uint32_t a[4];
            ldsm4(a, Ps_s + q_off + ks * 32);
            uint32_t vf[16];
            #pragma unroll
            for (int p = 0; p < 4; p++) ldsm4(vf + 4 * p, Vb_s + b_off[p] + ks * 32);
            #pragma unroll
            for (int nt = 0; nt < 8; nt++)
                mma_tf32(o[nt], a, &vf[2 * nt]);
        }
        __syncthreads();
    }

    // ---- epilogue: O/l -> g_y [B,T,C], tf32-rounded ----
    const float inv0 = 1.0f / l0, inv1 = 1.0f / l1;
    const int b = bh >> 4, h = bh & 15;
    const int t0 = q0 + wq + fr, t1 = t0 + 8;
    #pragma unroll
    for (int nt = 0; nt < 8; nt++) {
        const int d = nt * 8 + 2 * fc;
        *(float2*)(g_y + (size_t)(b * TDIM + t0) * CDIM + h * HD + d) =
            make_float2(__uint_as_float(cvt_tf32(o[nt][0] * inv0)),
                        __uint_as_float(cvt_tf32(o[nt][1] * inv0)));
        *(float2*)(g_y + (size_t)(b * TDIM + t1) * CDIM + h * HD + d) =
            make_float2(__uint_as_float(cvt_tf32(o[nt][2] * inv1)),
                        __uint_as_float(cvt_tf32(o[nt][3] * inv1)));
    }
}

// ================= launch =================
extern "C" void kernel_launch(void* const* d_in, const int* in_sizes, int n_in,
                              void* d_out, int out_size)
{
    const float* x     = (const float*)d_in[0];
    const float* sinp  = (const float*)d_in[1];
    const float* cosp  = (const float*)d_in[2];
    const float* Wqkv  = (const float*)d_in[3];
    const float* Wproj = (const float*)d_in[4];
    float* out = (float*)d_out;

    float* wt_qkv;  cudaGetSymbolAddress((void**)&wt_qkv,  g_wt_qkv);
    float* wt_proj; cudaGetSymbolAddress((void**)&wt_proj, g_wt_proj);

    cudaFuncSetAttribute(flash_mma,     cudaFuncAttributeMaxDynamicSharedMemorySize, FA_SMEM);
    cudaFuncSetAttribute(gemm_qkv_mma,  cudaFuncAttributeMaxDynamicSharedMemorySize, GSMEM);
    cudaFuncSetAttribute(gemm_proj_mma, cudaFuncAttributeMaxDynamicSharedMemorySize, GSMEM);

    cvt_x32_kernel<<<MDIM * CDIM / 4 / 256, 256>>>(x);
    transpose_cvt<<<dim3(NQKV / 32, CDIM / 32), 256>>>(Wqkv,  wt_qkv,  NQKV);
    transpose_cvt<<<dim3(CDIM / 32, CDIM / 32), 256>>>(Wproj, wt_proj, CDIM);

    gemm_qkv_mma<<<dim3(NQKV / 128, MDIM / 128), 256, GSMEM>>>(sinp, cosp);
    flash_mma<<<dim3(BDIM * NH, TDIM / 64), 128, FA_SMEM>>>();
    gemm_proj_mma<<<dim3(CDIM / 128, MDIM / 128), 256, GSMEM>>>(out);
}

// round 13
// speedup vs baseline: 4.0881x; 1.0673x over previous
#include <cuda_runtime.h>
#include <cstdint>
#include <math.h>

#define BDIM 2
#define TDIM 2048
#define CDIM 1024
#define NH 16
#define HD 64
#define MDIM (BDIM*TDIM)   // 4096
#define NQKV (3*CDIM)      // 3072

// Scratch (allocation-free rule: __device__ globals)
__device__ float g_q[BDIM*NH*TDIM*HD];    // pre-scaled by 0.125
__device__ float g_k[BDIM*NH*TDIM*HD];
__device__ float g_vt[BDIM*NH*HD*TDIM];   // V transposed: [bh][d][t]
__device__ float g_y[MDIM*CDIM];          // tf32-rounded by flash epilogue
__device__ float g_x32[MDIM*CDIM];        // x, tf32-rounded
__device__ float g_wt_qkv[NQKV*CDIM];     // W_qkv^T [N][K], tf32-rounded
__device__ float g_wt_proj[CDIM*CDIM];    // W_proj^T [N][K], tf32-rounded

__device__ __forceinline__ uint32_t cvt_tf32(float x) {
    uint32_t r; asm("cvt.rna.tf32.f32 %0, %1;" : "=r"(r) : "f"(x)); return r;
}
__device__ __forceinline__ void mma_tf32(float* d, const uint32_t* a, const uint32_t* b) {
    asm volatile(
        "mma.sync.aligned.m16n8k8.row.col.f32.tf32.tf32.f32 "
        "{%0,%1,%2,%3}, {%4,%5,%6,%7}, {%8,%9}, {%0,%1,%2,%3};"
        : "+f"(d[0]), "+f"(d[1]), "+f"(d[2]), "+f"(d[3])
        : "r"(a[0]), "r"(a[1]), "r"(a[2]), "r"(a[3]), "r"(b[0]), "r"(b[1]));
}
__device__ __forceinline__ void cp16(uint32_t daddr, const void* g) {
    asm volatile("cp.async.cg.shared.global [%0], [%1], 16;" :: "r"(daddr), "l"(g) : "memory");
}
__device__ __forceinline__ void ldsm4(uint32_t* r, uint32_t saddr) {
    asm volatile("ldmatrix.sync.aligned.m8n8.x4.shared.b16 {%0,%1,%2,%3}, [%4];"
        : "=r"(r[0]), "=r"(r[1]), "=r"(r[2]), "=r"(r[3]) : "r"(saddr));
}

// ================= pre-round x to tf32 =================
__global__ __launch_bounds__(256) void cvt_x32_kernel(const float* __restrict__ x)
{
    int i = blockIdx.x * 256 + threadIdx.x;
    float4 v = ((const float4*)x)[i];
    ((uint4*)g_x32)[i] = make_uint4(cvt_tf32(v.x), cvt_tf32(v.y), cvt_tf32(v.z), cvt_tf32(v.w));
}

// ================= transpose + tf32 convert =================
__global__ __launch_bounds__(256) void transpose_cvt(
    const float* __restrict__ W, float* __restrict__ WT, int N)
{
    __shared__ float t[32][33];
    int n0 = blockIdx.x * 32, k0 = blockIdx.y * 32;
    int tx = threadIdx.x & 31, ty = threadIdx.x >> 5;
    #pragma unroll
    for (int i = 0; i < 4; i++)
        t[ty + i * 8][tx] = W[(size_t)(k0 + ty + i * 8) * N + n0 + tx];
    __syncthreads();
    #pragma unroll
    for (int i = 0; i < 4; i++)
        WT[(size_t)(n0 + ty + i * 8) * CDIM + k0 + tx] =
            __uint_as_float(cvt_tf32(t[tx][ty + i * 8]));
}

// ================= tf32 mma.sync GEMM: BK=32, 3-stage cp.async + ldmatrix =================
// BM=BN=128, 8 warps (2x4), warp tile 64x32. smem [row][36] pad (banks 4r+c, conflict-free).
#define GPITCH (128*36)
#define GSMEM (6*GPITCH*4)     // 3 stages x (A+B) = 110592 B

__device__ __forceinline__ void gemm_issue(
    uint32_t* As, uint32_t* Bs, const float* Ap, const float* Bp,
    int stage, int k0, int lr2, int lc4)
{
    #pragma unroll
    for (int i = 0; i < 4; i++) {
        const int r = lr2 + i * 32;
        cp16((uint32_t)__cvta_generic_to_shared(As + stage * GPITCH + r * 36 + lc4),
             Ap + (size_t)r * CDIM + k0 + lc4);
        cp16((uint32_t)__cvta_generic_to_shared(Bs + stage * GPITCH + r * 36 + lc4),
             Bp + (size_t)r * CDIM + k0 + lc4);
    }
    asm volatile("cp.async.commit_group;" ::: "memory");
}

__device__ __forceinline__ void mma_mainloop(
    const float* __restrict__ Ap, const float* __restrict__ Bp,
    float (&acc)[4][4][4], int tid, uint32_t* smem)
{
    uint32_t* As = smem;               // [3][128][36]
    uint32_t* Bs = smem + 3 * GPITCH;
    const uint32_t As_s = (uint32_t)__cvta_generic_to_shared(As);
    const uint32_t Bs_s = (uint32_t)__cvta_generic_to_shared(Bs);
    const int lane = tid & 31, wid = tid >> 5;
    const int wm = wid >> 2, wn = wid & 3;
    const int lr2 = tid >> 3, lc4 = (tid & 7) * 4;     // 32 rows x 8 float4 per pass
    const int lq = lane & 7, j = lane >> 3;

    uint32_t a_off[4], b_off[2];
    #pragma unroll
    for (int mt = 0; mt < 4; mt++)
        a_off[mt] = ((wm * 64 + mt * 16 + (j & 1) * 8 + lq) * 36 + (j >> 1) * 4) * 4;
    #pragma unroll
    for (int p = 0; p < 2; p++)
        b_off[p] = ((wn * 32 + (2 * p + (j >> 1)) * 8 + lq) * 36 + (j & 1) * 4) * 4;

    #pragma unroll
    for (int mt = 0; mt < 4; mt++)
        #pragma unroll
        for (int nt = 0; nt < 4; nt++)
            #pragma unroll
            for (int jj = 0; jj < 4; jj++) acc[mt][nt][jj] = 0.f;

    gemm_issue(As, Bs, Ap, Bp, 0, 0, lr2, lc4);
    gemm_issue(As, Bs, Ap, Bp, 1, 32, lr2, lc4);

    int cur = 0, nxt = 2;
    for (int it = 0; it < 32; it++) {
        if (it < 31) asm volatile("cp.async.wait_group 1;" ::: "memory");
        else         asm volatile("cp.async.wait_group 0;" ::: "memory");
        __syncthreads();
        if (it + 2 < 32) {
            gemm_issue(As, Bs, Ap, Bp, nxt, (it + 2) * 32, lr2, lc4);
            if (++nxt == 3) nxt = 0;
        }

        const uint32_t Ab = As_s + cur * (GPITCH * 4);
        const uint32_t Bb = Bs_s + cur * (GPITCH * 4);
        #pragma unroll
        for (int ks = 0; ks < 4; ks++) {
            uint32_t af[4][4];
            #pragma unroll
            for (int mt = 0; mt < 4; mt++) ldsm4(af[mt], Ab + a_off[mt] + ks * 32);
            uint32_t bf[8];
            #pragma unroll
            for (int p = 0; p < 2; p++) ldsm4(bf + 4 * p, Bb + b_off[p] + ks * 32);
            #pragma unroll
            for (int mt = 0; mt < 4; mt++)
                #pragma unroll
                for (int nt = 0; nt < 4; nt++)
                    mma_tf32(acc[mt][nt], af[mt], &bf[2 * nt]);
        }
        if (++cur == 3) cur = 0;
    }
}

__global__ __launch_bounds__(256) void gemm_qkv_mma(
    const float* __restrict__ sinp, const float* __restrict__ cosp)
{
    extern __shared__ uint32_t smu[];
    const int tid = threadIdx.x;
    const int m0 = blockIdx.y * 128, n0 = blockIdx.x * 128;
    float acc[4][4][4];
    mma_mainloop(g_x32 + (size_t)m0 * CDIM, g_wt_qkv + (size_t)n0 * CDIM, acc, tid, smu);

    const int lane = tid & 31, wid = tid >> 5;
    const int wm = wid >> 2, wn = wid & 3;
    const int sec = n0 >> 10;
    const int nb = n0 & 1023;

    #pragma unroll
    for (int mt = 0; mt < 4; mt++) {
        #pragma unroll
        for (int nt = 0; nt < 4; nt++) {
            const int col = wn * 32 + nt * 8 + (lane & 3) * 2;
            const int nc = nb + col;
            const int h = nc >> 6, d = nc & 63;
            #pragma unroll
            for (int half = 0; half < 2; half++) {
                const int row = m0 + wm * 64 + mt * 16 + (lane >> 2) + half * 8;
                const int b = row >> 11, t = row & 2047;
                const int bh = b * NH + h;
                float v0 = acc[mt][nt][half * 2], v1 = acc[mt][nt][half * 2 + 1];
                if (sec < 2) {
                    float ca = cosp[t * HD + d], sa = sinp[t * HD + d];
                    float o0 = v0 * ca - v1 * sa;
                    float o1 = v1 * ca + v0 * sa;
                    if (sec == 0) { o0 *= 0.125f; o1 *= 0.125f; }   // fold softmax scale (exact)
                    float* dst = (sec == 0) ? g_q : g_k;
                    *(float2*)(dst + (((size_t)bh * TDIM + t) * HD + d)) =
                        make_float2(__uint_as_float(cvt_tf32(o0)), __uint_as_float(cvt_tf32(o1)));
                } else {
                    g_vt[((size_t)bh * HD + d) * TDIM + t]     = __uint_as_float(cvt_tf32(v0));
                    g_vt[((size_t)bh * HD + d + 1) * TDIM + t] = __uint_as_float(cvt_tf32(v1));
                }
            }
        }
    }
}

__global__ __launch_bounds__(256) void gemm_proj_mma(float* __restrict__ out)
{
    extern __shared__ uint32_t smu[];
    const int tid = threadIdx.x;
    const int m0 = blockIdx.y * 128, n0 = blockIdx.x * 128;
    float acc[4][4][4];
    mma_mainloop(g_y + (size_t)m0 * CDIM, g_wt_proj + (size_t)n0 * CDIM, acc, tid, smu);

    const int lane = tid & 31, wid = tid >> 5;
    const int wm = wid >> 2, wn = wid & 3;
    #pragma unroll
    for (int mt = 0; mt < 4; mt++) {
        #pragma unroll
        for (int nt = 0; nt < 4; nt++) {
            const int col = n0 + wn * 32 + nt * 8 + (lane & 3) * 2;
            #pragma unroll
            for (int half = 0; half < 2; half++) {
                const int row = m0 + wm * 64 + mt * 16 + (lane >> 2) + half * 8;
                *(float2*)(out + (size_t)row * CDIM + col) =
                    make_float2(acc[mt][nt][half * 2], acc[mt][nt][half * 2 + 1]);
            }
        }
    }
}

// ================= flash attention: mma.sync tf32, full-ldmatrix =================
// CTA: 64 q-rows, 4 warps (warp = 16 q x 64 k). BK=64, cp.async double buffer.
// Q is pre-scaled by 0.125 (folded softmax scale).
#define FA_SMEM 104448

__global__ __launch_bounds__(128) void flash_mma()
{
    extern __shared__ float sm[];
    float* Qs = sm;                 // [64][68]
    float* Ps = sm + 4352;          // [64][68]
    float* KsB = sm + 8704;         // [2][64][68]
    float* VsB = sm + 17408;        // [2][64][68]  (Vt: rows=d, cols=t)

    const int bh = blockIdx.x;
    const int qt = 31 - blockIdx.y;         // long CTAs first
    const int q0 = qt * 64;
    const int tid = threadIdx.x;
    const int lane = tid & 31, wid = tid >> 5;
    const int fr = lane >> 2, fc = lane & 3;
    const int lq = lane & 7, j = lane >> 3;
    const int wq = wid * 16;

    const float* qb = g_q + (size_t)bh * TDIM * HD;
    const float* kb = g_k + (size_t)bh * TDIM * HD;
    const float* vtb = g_vt + (size_t)bh * HD * TDIM;

    const uint32_t Qs_s = (uint32_t)__cvta_generic_to_shared(Qs);
    const uint32_t Ps_s = (uint32_t)__cvta_generic_to_shared(Ps);
    const uint32_t Ks_s = (uint32_t)__cvta_generic_to_shared(KsB);
    const uint32_t Vs_s = (uint32_t)__cvta_generic_to_shared(VsB);

    const uint32_t q_off = ((wq + (j & 1) * 8 + lq) * 68 + (j >> 1) * 4) * 4;
    uint32_t b_off[4];
    #pragma unroll
    for (int p = 0; p < 4; p++)
        b_off[p] = (((2 * p + (j >> 1)) * 8 + lq) * 68 + (j & 1) * 4) * 4;

    #pragma unroll
    for (int i = 0; i < 8; i++) {
        int lin = tid + i * 128;
        int r = lin >> 4, c4 = (lin & 15) * 4;
        *(float4*)(Qs + r * 68 + c4) = *(const float4*)(qb + (size_t)(q0 + r) * HD + c4);
    }
    #pragma unroll
    for (int i = 0; i < 8; i++) {
        int lin = tid + i * 128;
        int r = lin >> 4, c4 = (lin & 15) * 4;
        cp16((uint32_t)__cvta_generic_to_shared(KsB + r * 68 + c4),
             kb + (size_t)r * HD + c4);
        cp16((uint32_t)__cvta_generic_to_shared(VsB + r * 68 + c4),
             vtb + (size_t)r * TDIM + c4);
    }
    asm volatile("cp.async.commit_group;" ::: "memory");

    float o[8][4];
    #pragma unroll
    for (int nt = 0; nt < 8; nt++)
        #pragma unroll
        for (int jj = 0; jj < 4; jj++) o[nt][jj] = 0.f;
    float m0 = -1e30f, m1 = -1e30f, l0 = 0.f, l1 = 0.f;

    for (int kt = 0; kt <= qt; kt++) {
        const int buf = kt & 1;
        if (kt < qt) {
            const int kr = (kt + 1) * 64;
            float* Kn = KsB + (buf ^ 1) * 4352;
            float* Vn = VsB + (buf ^ 1) * 4352;
            #pragma unroll
            for (int i = 0; i < 8; i++) {
                int lin = tid + i * 128;
                int r = lin >> 4, c4 = (lin & 15) * 4;
                cp16((uint32_t)__cvta_generic_to_shared(Kn + r * 68 + c4),
                     kb + (size_t)(kr + r) * HD + c4);
                cp16((uint32_t)__cvta_generic_to_shared(Vn + r * 68 + c4),
                     vtb + (size_t)r * TDIM + kr + c4);
            }
            asm volatile("cp.async.commit_group;" ::: "memory");
            asm volatile("cp.async.wait_group 1;" ::: "memory");
        } else {
            asm volatile("cp.async.wait_group 0;" ::: "memory");
        }
        __syncthreads();

        const uint32_t Kb_s = Ks_s + buf * (4352 * 4);
        const uint32_t Vb_s = Vs_s + buf * (4352 * 4);

        // ---- S = Q K^T  (scale pre-folded into Q) ----
        float s[8][4];
        #pragma unroll
        for (int nt = 0; nt < 8; nt++)
            #pragma unroll
            for (int jj = 0; jj < 4; jj++) s[nt][jj] = 0.f;
        #pragma unroll
        for (int ks = 0; ks < 8; ks++) {
            uint32_t a[4];
            ldsm4(a, Qs_s + q_off + ks * 32);
            uint32_t kf[16];
            #pragma unroll
            for (int p = 0; p < 4; p++) ldsm4(kf + 4 * p, Kb_s + b_off[p] + ks * 32);
            #pragma unroll
            for (int nt = 0; nt < 8; nt++)
                mma_tf32(s[nt], a, &kf[2 * nt]);
        }

        if (kt == qt) {
            const int r0 = wq + fr, r1 = r0 + 8;
            #pragma unroll
            for (int nt = 0; nt < 8; nt++) {
                const int cl = nt * 8 + 2 * fc;
                if (cl > r0)     s[nt][0] = -1e30f;
                if (cl + 1 > r0) s[nt][1] = -1e30f;
                if (cl > r1)     s[nt][2] = -1e30f;
                if (cl + 1 > r1) s[nt][3] = -1e30f;
            }
        }

        // ---- online softmax (warp-local quad shuffles) ----
        float mx0 = -1e30f, mx1 = -1e30f;
        #pragma unroll
        for (int nt = 0; nt < 8; nt++) {
            mx0 = fmaxf(mx0, fmaxf(s[nt][0], s[nt][1]));
            mx1 = fmaxf(mx1, fmaxf(s[nt][2], s[nt][3]));
        }
        mx0 = fmaxf(mx0, __shfl_xor_sync(0xffffffffu, mx0, 1));
        mx0 = fmaxf(mx0, __shfl_xor_sync(0xffffffffu, mx0, 2));
        mx1 = fmaxf(mx1, __shfl_xor_sync(0xffffffffu, mx1, 1));
        mx1 = fmaxf(mx1, __shfl_xor_sync(0xffffffffu, mx1, 2));
        const float mn0 = fmaxf(m0, mx0), mn1 = fmaxf(m1, mx1);
        const float al0 = __expf(m0 - mn0), al1 = __expf(m1 - mn1);
        m0 = mn0; m1 = mn1;

        float ps0 = 0.f, ps1 = 0.f;
        #pragma unroll
        for (int nt = 0; nt < 8; nt++) {
            float p0 = __expf(s[nt][0] - mn0);
            float p1 = __expf(s[nt][1] - mn0);
            float p2 = __expf(s[nt][2] - mn1);
            float p3 = __expf(s[nt][3] - mn1);
            ps0 += p0 + p1; ps1 += p2 + p3;
            const int cl = nt * 8 + 2 * fc;
            Ps[(wq + fr) * 68 + cl]     = p0;
            Ps[(wq + fr) * 68 + cl + 1] = p1;
            Ps[(wq + fr + 8) * 68 + cl]     = p2;
            Ps[(wq + fr + 8) * 68 + cl + 1] = p3;
        }
        ps0 += __shfl_xor_sync(0xffffffffu, ps0, 1);
        ps0 += __shfl_xor_sync(0xffffffffu, ps0, 2);
        ps1 += __shfl_xor_sync(0xffffffffu, ps1, 1);
        ps1 += __shfl_xor_sync(0xffffffffu, ps1, 2);
        l0 = l0 * al0 + ps0;
        l1 = l1 * al1 + ps1;
        #pragma unroll
        for (int nt = 0; nt < 8; nt++) {
            o[nt][0] *= al0; o[nt][1] *= al0;
            o[nt][2] *= al1; o[nt][3] *= al1;
        }
        __syncwarp();

        // ---- O += P V  (ldmatrix on Vt) ----
        #pragma unroll
        for (int ks = 0; ks < 8; ks++) {
            uint32_t a[4];
            ldsm4(a, Ps_s + q_off + ks * 32);
            uint32_t vf[16];
            #pragma unroll
            for (int p = 0; p < 4; p++) ldsm4(vf + 4 * p, Vb_s + b_off[p] + ks * 32);
            #pragma unroll
            for (int nt = 0; nt < 8; nt++)
                mma_tf32(o[nt], a, &vf[2 * nt]);
        }
        __syncthreads();
    }

    // ---- epilogue: O/l -> g_y [B,T,C], tf32-rounded ----
    const float inv0 = 1.0f / l0, inv1 = 1.0f / l1;
    const int b = bh >> 4, h = bh & 15;
    const int t0 = q0 + wq + fr, t1 = t0 + 8;
    #pragma unroll
    for (int nt = 0; nt < 8; nt++) {
        const int d = nt * 8 + 2 * fc;
        *(float2*)(g_y + (size_t)(b * TDIM + t0) * CDIM + h * HD + d) =
            make_float2(__uint_as_float(cvt_tf32(o[nt][0] * inv0)),
                        __uint_as_float(cvt_tf32(o[nt][1] * inv0)));
        *(float2*)(g_y + (size_t)(b * TDIM + t1) * CDIM + h * HD + d) =
            make_float2(__uint_as_float(cvt_tf32(o[nt][2] * inv1)),
                        __uint_as_float(cvt_tf32(o[nt][3] * inv1)));
    }
}

// ================= launch =================
extern "C" void kernel_launch(void* const* d_in, const int* in_sizes, int n_in,
                              void* d_out, int out_size)
{
    const float* x     = (const float*)d_in[0];
    const float* sinp  = (const float*)d_in[1];
    const float* cosp  = (const float*)d_in[2];
    const float* Wqkv  = (const float*)d_in[3];
    const float* Wproj = (const float*)d_in[4];
    float* out = (float*)d_out;

    float* wt_qkv;  cudaGetSymbolAddress((void**)&wt_qkv,  g_wt_qkv);
    float* wt_proj; cudaGetSymbolAddress((void**)&wt_proj, g_wt_proj);

    cudaFuncSetAttribute(flash_mma,     cudaFuncAttributeMaxDynamicSharedMemorySize, FA_SMEM);
    cudaFuncSetAttribute(gemm_qkv_mma,  cudaFuncAttributeMaxDynamicSharedMemorySize, GSMEM);
    cudaFuncSetAttribute(gemm_proj_mma, cudaFuncAttributeMaxDynamicSharedMemorySize, GSMEM);

    cvt_x32_kernel<<<MDIM * CDIM / 4 / 256, 256>>>(x);
    transpose_cvt<<<dim3(NQKV / 32, CDIM / 32), 256>>>(Wqkv,  wt_qkv,  NQKV);
    transpose_cvt<<<dim3(CDIM / 32, CDIM / 32), 256>>>(Wproj, wt_proj, CDIM);

    gemm_qkv_mma<<<dim3(NQKV / 128, MDIM / 128), 256, GSMEM>>>(sinp, cosp);
    flash_mma<<<dim3(BDIM * NH, TDIM / 64), 128, FA_SMEM>>>();
    gemm_proj_mma<<<dim3(CDIM / 128, MDIM / 128), 256, GSMEM>>>(out);
}